// round 1
// baseline (speedup 1.0000x reference)
#include <cuda_runtime.h>
#include <math.h>

// Problem constants
#define NB 8
#define TFULL 16384
// lengths: causal out 16383, first gated 16382, after 9 dilated layers 15360

// ---------------- scratch (device globals; no allocation allowed) ----------------
__device__ float g_h0[33554432];          // 8*16384*256  (causal output, padded rows)
__device__ float g_p0[3145728];           // 8*16384*24   ping
__device__ float g_p1[3145728];           // 8*16384*24   pong
__device__ float g_accb[15728640];        // 8*15360*128  relu(res conv)
__device__ float g_a2[31457280];          // 8*15360*256  relu(f1)

// =====================================================================
// Generic fp32 GEMM:  C[m, n] = act( sum_k A[m*Arow + k] * W[k*256 + n] + bias[n] )
// N fixed = 256 (grid.x = 2 tiles of 128). BM=128, BN=128, BK=8, 256 thr, 8x8/thread.
// A rows are read as K *contiguous* floats starting at row base (works for the
// causal conv where K=512 spans two adjacent 256-float rows).
// =====================================================================
template<int ACT>
__global__ void gemm_bias_k(const float* __restrict__ A, long long Abstride,
                            int M, int K, int Arow,
                            const float* __restrict__ W, const float* __restrict__ bias,
                            float* __restrict__ C, long long Cbstride, int Crow)
{
    const int b  = blockIdx.z;
    A += (long long)b * Abstride;
    C += (long long)b * Cbstride;
    const int m0 = blockIdx.y * 128;
    const int n0 = blockIdx.x * 128;

    __shared__ __align__(16) float As[8][128];
    __shared__ __align__(16) float Bs[8][128];

    const int tid  = threadIdx.x;
    const int tr   = tid >> 4;          // 0..15
    const int tc   = tid & 15;          // 0..15
    const int arow = tid >> 1;          // 0..127
    const int akq  = (tid & 1) * 4;     // 0 or 4
    const int brow = tid >> 5;          // 0..7
    const int bcol = (tid & 31) * 4;    // 0..124

    int mload = m0 + arow; if (mload > M - 1) mload = M - 1;
    const float* Ap = A + (long long)mload * Arow;

    float acc[8][8];
#pragma unroll
    for (int i = 0; i < 8; i++)
#pragma unroll
        for (int j = 0; j < 8; j++) acc[i][j] = 0.f;

    for (int k0 = 0; k0 < K; k0 += 8) {
        float4 av = *reinterpret_cast<const float4*>(Ap + k0 + akq);
        As[akq + 0][arow] = av.x;
        As[akq + 1][arow] = av.y;
        As[akq + 2][arow] = av.z;
        As[akq + 3][arow] = av.w;
        float4 bv = *reinterpret_cast<const float4*>(W + (long long)(k0 + brow) * 256 + n0 + bcol);
        *reinterpret_cast<float4*>(&Bs[brow][bcol]) = bv;
        __syncthreads();
#pragma unroll
        for (int k = 0; k < 8; k++) {
            float a[8], w[8];
            *reinterpret_cast<float4*>(a)     = *reinterpret_cast<const float4*>(&As[k][tr * 8]);
            *reinterpret_cast<float4*>(a + 4) = *reinterpret_cast<const float4*>(&As[k][tr * 8 + 4]);
            *reinterpret_cast<float4*>(w)     = *reinterpret_cast<const float4*>(&Bs[k][tc * 8]);
            *reinterpret_cast<float4*>(w + 4) = *reinterpret_cast<const float4*>(&Bs[k][tc * 8 + 4]);
#pragma unroll
            for (int i = 0; i < 8; i++)
#pragma unroll
                for (int j = 0; j < 8; j++) acc[i][j] += a[i] * w[j];
        }
        __syncthreads();
    }

#pragma unroll
    for (int i = 0; i < 8; i++) {
        int m = m0 + tr * 8 + i;
        if (m < M) {
            float* Cp = C + (long long)m * Crow + n0 + tc * 8;
#pragma unroll
            for (int j = 0; j < 8; j++) {
                float v = acc[i][j] + bias[n0 + tc * 8 + j];
                if (ACT == 1) v = fmaxf(v, 0.f);
                Cp[j] = v;
            }
        }
    }
}

// =====================================================================
// First gated layer: input h0 (per-batch 16383 rows x 256, stride 256).
// For t: concat(h0[t], h0[t+1]) (512 contiguous) x [Wg | Wf] (512x48),
// p = tanh(f+fb)*sigmoid(g+gb), out = p x S (24x24) + sb.
// BM=128 timesteps per block, 256 threads, thread tile 4t x (3g+3f paired cols).
// =====================================================================
__global__ void first_gated_k(const float* __restrict__ h0,
                              const float* __restrict__ gW, const float* __restrict__ gb,
                              const float* __restrict__ fW, const float* __restrict__ fb,
                              const float* __restrict__ sW, const float* __restrict__ sb,
                              float* __restrict__ out)
{
    const int M  = 16382;
    const int b  = blockIdx.y;
    const int m0 = blockIdx.x * 128;
    const float* A = h0 + (long long)b * 16384 * 256;

    __shared__ __align__(16) float As[8][128];
    __shared__ __align__(16) float Bs[8][48];
    __shared__ float P[128][25];

    const int tid = threadIdx.x;
    const int tr  = tid >> 3;     // 0..31 -> rows tr*4..+3
    const int tc  = tid & 7;      // 0..7  -> cols tc*3..+2 (both g and f halves)
    const int arow = tid >> 1;
    const int akq  = (tid & 1) * 4;

    int mload = m0 + arow; if (mload > M - 1) mload = M - 1;
    const float* Ap = A + (long long)mload * 256;

    float accG[4][3], accF[4][3];
#pragma unroll
    for (int i = 0; i < 4; i++)
#pragma unroll
        for (int j = 0; j < 3; j++) { accG[i][j] = 0.f; accF[i][j] = 0.f; }

    for (int k0 = 0; k0 < 512; k0 += 8) {
        float4 av = *reinterpret_cast<const float4*>(Ap + k0 + akq);
        As[akq + 0][arow] = av.x;
        As[akq + 1][arow] = av.y;
        As[akq + 2][arow] = av.z;
        As[akq + 3][arow] = av.w;
        if (tid < 96) {
            int kk = tid / 12, n = (tid % 12) * 4;
            const float* srcp = (n < 24) ? (gW + (long long)(k0 + kk) * 24 + n)
                                         : (fW + (long long)(k0 + kk) * 24 + (n - 24));
            *reinterpret_cast<float4*>(&Bs[kk][n]) = *reinterpret_cast<const float4*>(srcp);
        }
        __syncthreads();
#pragma unroll
        for (int k = 0; k < 8; k++) {
            float a[4];
            *reinterpret_cast<float4*>(a) = *reinterpret_cast<const float4*>(&As[k][tr * 4]);
            float wg[3], wf[3];
#pragma unroll
            for (int j = 0; j < 3; j++) { wg[j] = Bs[k][tc * 3 + j]; wf[j] = Bs[k][24 + tc * 3 + j]; }
#pragma unroll
            for (int i = 0; i < 4; i++)
#pragma unroll
                for (int j = 0; j < 3; j++) {
                    accG[i][j] += a[i] * wg[j];
                    accF[i][j] += a[i] * wf[j];
                }
        }
        __syncthreads();
    }

#pragma unroll
    for (int i = 0; i < 4; i++)
#pragma unroll
        for (int j = 0; j < 3; j++) {
            float g = accG[i][j] + gb[tc * 3 + j];
            float f = accF[i][j] + fb[tc * 3 + j];
            P[tr * 4 + i][tc * 3 + j] = tanhf(f) / (1.f + expf(-g));
        }
    __syncthreads();

    float acc2[4][3];
#pragma unroll
    for (int i = 0; i < 4; i++)
#pragma unroll
        for (int j = 0; j < 3; j++) acc2[i][j] = 0.f;
#pragma unroll
    for (int k = 0; k < 24; k++) {
        float a[4];
#pragma unroll
        for (int i = 0; i < 4; i++) a[i] = P[tr * 4 + i][k];
        float w0 = sW[k * 24 + tc * 3 + 0];
        float w1 = sW[k * 24 + tc * 3 + 1];
        float w2 = sW[k * 24 + tc * 3 + 2];
#pragma unroll
        for (int i = 0; i < 4; i++) {
            acc2[i][0] += a[i] * w0;
            acc2[i][1] += a[i] * w1;
            acc2[i][2] += a[i] * w2;
        }
    }
    float* O = out + (long long)b * 16384 * 24;
#pragma unroll
    for (int i = 0; i < 4; i++) {
        int m = m0 + tr * 4 + i;
        if (m < M) {
#pragma unroll
            for (int j = 0; j < 3; j++)
                O[(long long)m * 24 + tc * 3 + j] = acc2[i][j] + sb[tc * 3 + j];
        }
    }
}

// =====================================================================
// Dilated gated 24-ch layer. Inputs at t and t+d gathered into smem
// (transposed [j48][t]), weights fused as Wc[48][48] = [Wg | Wf].
// =====================================================================
__global__ void gated24_k(const float* __restrict__ in, float* __restrict__ out,
                          int Lin, int Lout, int d,
                          const float* __restrict__ gW, const float* __restrict__ gb,
                          const float* __restrict__ fW, const float* __restrict__ fb,
                          const float* __restrict__ sW, const float* __restrict__ sb)
{
    const int b  = blockIdx.y;
    const int m0 = blockIdx.x * 128;
    const float* Ab = in + (long long)b * 16384 * 24;

    __shared__ float As[48][129];   // [j48][t]
    __shared__ float Wc[48][48];
    __shared__ float P[128][25];

    const int tid = threadIdx.x;

    for (int i = tid; i < 2304; i += 256) {
        int j48 = i / 48, c48 = i % 48;
        int k = j48 / 24, j = j48 % 24;
        Wc[j48][c48] = (c48 < 24) ? gW[(k * 24 + j) * 24 + c48]
                                  : fW[(k * 24 + j) * 24 + (c48 - 24)];
    }

    int lim0 = (Lin - m0) * 24;       if (lim0 > 3072) lim0 = 3072;
    int lim1 = (Lin - m0 - d) * 24;   if (lim1 > 3072) lim1 = 3072; if (lim1 < 0) lim1 = 0;
    const float* s0 = Ab + (long long)m0 * 24;
    const float* s1 = s0 + (long long)d * 24;
    for (int i = tid; i < 3072; i += 256) {
        int t = i / 24, j = i % 24;
        As[j][t]      = (i < lim0) ? s0[i] : 0.f;
        As[24 + j][t] = (i < lim1) ? s1[i] : 0.f;
    }
    __syncthreads();

    const int tr = tid >> 3;   // 0..31
    const int tc = tid & 7;    // 0..7

    float accG[4][3], accF[4][3];
#pragma unroll
    for (int i = 0; i < 4; i++)
#pragma unroll
        for (int j = 0; j < 3; j++) { accG[i][j] = 0.f; accF[i][j] = 0.f; }

#pragma unroll
    for (int k = 0; k < 48; k++) {
        float a[4];
#pragma unroll
        for (int i = 0; i < 4; i++) a[i] = As[k][tr * 4 + i];
        float wg[3], wf[3];
#pragma unroll
        for (int j = 0; j < 3; j++) { wg[j] = Wc[k][tc * 3 + j]; wf[j] = Wc[k][24 + tc * 3 + j]; }
#pragma unroll
        for (int i = 0; i < 4; i++)
#pragma unroll
            for (int j = 0; j < 3; j++) {
                accG[i][j] += a[i] * wg[j];
                accF[i][j] += a[i] * wf[j];
            }
    }

#pragma unroll
    for (int i = 0; i < 4; i++)
#pragma unroll
        for (int j = 0; j < 3; j++) {
            float g = accG[i][j] + gb[tc * 3 + j];
            float f = accF[i][j] + fb[tc * 3 + j];
            P[tr * 4 + i][tc * 3 + j] = tanhf(f) / (1.f + expf(-g));
        }
    __syncthreads();

    float acc2[4][3];
#pragma unroll
    for (int i = 0; i < 4; i++)
#pragma unroll
        for (int j = 0; j < 3; j++) acc2[i][j] = 0.f;
#pragma unroll
    for (int k = 0; k < 24; k++) {
        float a[4];
#pragma unroll
        for (int i = 0; i < 4; i++) a[i] = P[tr * 4 + i][k];
        float w0 = sW[k * 24 + tc * 3 + 0];
        float w1 = sW[k * 24 + tc * 3 + 1];
        float w2 = sW[k * 24 + tc * 3 + 2];
#pragma unroll
        for (int i = 0; i < 4; i++) {
            acc2[i][0] += a[i] * w0;
            acc2[i][1] += a[i] * w1;
            acc2[i][2] += a[i] * w2;
        }
    }
    float* O = out + (long long)b * 16384 * 24;
#pragma unroll
    for (int i = 0; i < 4; i++) {
        int m = m0 + tr * 4 + i;
        if (m < Lout) {
#pragma unroll
            for (int j = 0; j < 3; j++)
                O[(long long)m * 24 + tc * 3 + j] = acc2[i][j] + sb[tc * 3 + j];
        }
    }
}

// =====================================================================
// Residual + ReLU:  a[t, c] = relu( (prev[t+256] + cur[t]) x R(24x128) + rb )
// Lout = 15360 exactly, tiles 128x128, K=24.
// =====================================================================
__global__ void res_relu_k(const float* __restrict__ prev, const float* __restrict__ cur,
                           const float* __restrict__ R, const float* __restrict__ rb,
                           float* __restrict__ outa)
{
    const int b  = blockIdx.y;
    const int m0 = blockIdx.x * 128;
    const float* Pp = prev + (long long)b * 16384 * 24 + (long long)(m0 + 256) * 24;
    const float* Cp = cur  + (long long)b * 16384 * 24 + (long long)m0 * 24;

    __shared__ float As[24][129];                 // [k][t]
    __shared__ __align__(16) float Bs[24][128];

    const int tid = threadIdx.x;
    for (int i = tid; i < 3072; i += 256) {
        int t = i / 24, j = i % 24;
        As[j][t] = Pp[i] + Cp[i];
    }
    for (int i = tid; i < 3072; i += 256) Bs[i >> 7][i & 127] = R[i];
    __syncthreads();

    const int tr = tid >> 4, tc = tid & 15;
    float acc[8][8];
#pragma unroll
    for (int i = 0; i < 8; i++)
#pragma unroll
        for (int j = 0; j < 8; j++) acc[i][j] = 0.f;

#pragma unroll
    for (int k = 0; k < 24; k++) {
        float a[8], w[8];
#pragma unroll
        for (int i = 0; i < 8; i++) a[i] = As[k][tr * 8 + i];
        *reinterpret_cast<float4*>(w)     = *reinterpret_cast<const float4*>(&Bs[k][tc * 8]);
        *reinterpret_cast<float4*>(w + 4) = *reinterpret_cast<const float4*>(&Bs[k][tc * 8 + 4]);
#pragma unroll
        for (int i = 0; i < 8; i++)
#pragma unroll
            for (int j = 0; j < 8; j++) acc[i][j] += a[i] * w[j];
    }

    float* O = outa + (long long)b * 15360 * 128 + (long long)m0 * 128;
#pragma unroll
    for (int i = 0; i < 8; i++)
#pragma unroll
        for (int j = 0; j < 8; j++)
            O[(long long)(tr * 8 + i) * 128 + tc * 8 + j] = fmaxf(acc[i][j] + rb[tc * 8 + j], 0.f);
}

// =====================================================================
// In-place softmax over 256 channels; one block per row.
// =====================================================================
__global__ void softmax256_k(float* __restrict__ io)
{
    float* p = io + (long long)blockIdx.x * 256;
    const int tid = threadIdx.x;
    __shared__ float red[8];
    __shared__ float bval;

    float v = p[tid];
    float m = v;
#pragma unroll
    for (int o = 16; o; o >>= 1) m = fmaxf(m, __shfl_xor_sync(0xffffffffu, m, o));
    if ((tid & 31) == 0) red[tid >> 5] = m;
    __syncthreads();
    if (tid == 0) {
        float t = red[0];
#pragma unroll
        for (int i = 1; i < 8; i++) t = fmaxf(t, red[i]);
        bval = t;
    }
    __syncthreads();
    m = bval;
    float e = expf(v - m);
    float s = e;
#pragma unroll
    for (int o = 16; o; o >>= 1) s += __shfl_xor_sync(0xffffffffu, s, o);
    if ((tid & 31) == 0) red[tid >> 5] = s;
    __syncthreads();
    if (tid == 0) {
        float t = 0.f;
#pragma unroll
        for (int i = 0; i < 8; i++) t += red[i];
        bval = t;
    }
    __syncthreads();
    p[tid] = e / bval;
}

// =====================================================================
extern "C" void kernel_launch(void* const* d_in, const int* in_sizes, int n_in,
                              void* d_out, int out_size)
{
    const float* x        = (const float*)d_in[0];
    const float* causal_W = (const float*)d_in[1];
    const float* causal_b = (const float*)d_in[2];
    const float* gW0      = (const float*)d_in[3];
    const float* gb0      = (const float*)d_in[4];
    const float* fW0      = (const float*)d_in[5];
    const float* fb0      = (const float*)d_in[6];
    const float* sW0      = (const float*)d_in[7];
    const float* sb0      = (const float*)d_in[8];
    const float* gate_W   = (const float*)d_in[9];
    const float* gate_b   = (const float*)d_in[10];
    const float* filter_W = (const float*)d_in[11];
    const float* filter_b = (const float*)d_in[12];
    const float* scale_W  = (const float*)d_in[13];
    const float* scale_b  = (const float*)d_in[14];
    const float* res_W    = (const float*)d_in[15];
    const float* res_b    = (const float*)d_in[16];
    const float* f1_W     = (const float*)d_in[17];
    const float* f1_b     = (const float*)d_in[18];
    const float* f2_W     = (const float*)d_in[19];
    const float* f2_b     = (const float*)d_in[20];
    float* out = (float*)d_out;

    float *h0, *p0, *p1, *accb, *a2b;
    cudaGetSymbolAddress((void**)&h0,   g_h0);
    cudaGetSymbolAddress((void**)&p0,   g_p0);
    cudaGetSymbolAddress((void**)&p1,   g_p1);
    cudaGetSymbolAddress((void**)&accb, g_accb);
    cudaGetSymbolAddress((void**)&a2b,  g_a2);

    // 1) causal conv as GEMM: M=16383/batch, K=512, N=256
    gemm_bias_k<0><<<dim3(2, 128, 8), 256>>>(x, 16384LL * 256, 16383, 512, 256,
                                             causal_W, causal_b, h0, 16384LL * 256, 256);

    // 2) first gated layer -> p0 (16382 rows/batch)
    first_gated_k<<<dim3(128, 8), 256>>>(h0, gW0, gb0, fW0, fb0, sW0, sb0, p0);

    // 3) nine dilated gated layers (only last residual matters)
    float* bufs[2] = { p0, p1 };
    int cur = 0;
    int Lin = 16382;
    for (int i = 0; i < 9; i++) {
        int d = 2 << i;           // 2,4,...,512
        int Lout = Lin - d;
        gated24_k<<<dim3((Lout + 127) / 128, 8), 256>>>(
            bufs[cur], bufs[1 - cur], Lin, Lout, d,
            gate_W + i * 1152, gate_b + i * 24,
            filter_W + i * 1152, filter_b + i * 24,
            scale_W + i * 576, scale_b + i * 24);
        cur ^= 1;
        Lin = Lout;
    }
    // now bufs[cur] = out of layer i=8 (15360 rows), bufs[1-cur] = its input (15872 rows)

    // 4) residual combine + res conv (i=8 only) + ReLU -> accb (15360 x 128)
    res_relu_k<<<dim3(120, 8), 256>>>(bufs[1 - cur], bufs[cur],
                                      res_W + 8 * 24 * 128, res_b + 8 * 128, accb);

    // 5) f1: K=128 N=256 + ReLU -> a2b
    gemm_bias_k<1><<<dim3(2, 960, 1), 256>>>(accb, 0, 122880, 128, 128,
                                             f1_W, f1_b, a2b, 0, 256);

    // 6) f2: K=256 N=256 -> logits in d_out
    gemm_bias_k<0><<<dim3(2, 960, 1), 256>>>(a2b, 0, 122880, 256, 256,
                                             f2_W, f2_b, out, 0, 256);

    // 7) softmax over channels, in place
    softmax256_k<<<122880, 256>>>(out);
}

// round 5
// speedup vs baseline: 1.6750x; 1.6750x over previous
#include <cuda_runtime.h>
#include <cstdint>
#include <math.h>

// ---------------- scratch (device globals; no allocation allowed) ----------------
__device__ float g_h0[33554432];          // 8*16384*256  (causal output)
__device__ float g_p0[3145728];           // 8*16384*24   ping
__device__ float g_p1[3145728];           // 8*16384*24   pong
__device__ float g_accb[15728640];        // 8*15360*128  relu(res conv)
__device__ float g_a2[31457280];          // 8*15360*256  relu(f1)

__device__ __forceinline__ uint32_t f2tf(float f) {
    uint32_t r; asm("cvt.rna.tf32.f32 %0, %1;" : "=r"(r) : "f"(f)); return r;
}

__device__ __forceinline__ void mma_tf32_16x8x8(float c[4],
                                                const uint32_t a[4], const uint32_t b[2])
{
    asm volatile(
        "mma.sync.aligned.m16n8k8.row.col.f32.tf32.tf32.f32 "
        "{%0,%1,%2,%3}, {%4,%5,%6,%7}, {%8,%9}, {%0,%1,%2,%3};"
        : "+f"(c[0]), "+f"(c[1]), "+f"(c[2]), "+f"(c[3])
        : "r"(a[0]), "r"(a[1]), "r"(a[2]), "r"(a[3]), "r"(b[0]), "r"(b[1]));
}

// =====================================================================
// tf32 mma.sync GEMM: C[m, n] = act( A[m..] (K contiguous from row base,
// row stride Arow) x W[K,256] + bias ), N=256 via grid.x=2 tiles of 128.
// BM=128, BN=128, BK=16, 256 threads (8 warps, 2x4), warp tile 64x32.
// ACT: 0 none, 1 relu.
// =====================================================================
template<int ACT>
__global__ void __launch_bounds__(256)
mma_gemm_k(const float* __restrict__ A, long long Abstride,
           int M, int K, int Arow,
           const float* __restrict__ W, const float* __restrict__ bias,
           float* __restrict__ C, long long Cbstride, int Crow)
{
    __shared__ __align__(16) float As[128][20];   // [m][k], pad 20 -> conflict-free frag loads
    __shared__ __align__(16) float Bs[16][136];   // [k][n], pad 136 -> conflict-free frag loads

    const int b = blockIdx.z;
    A += (long long)b * Abstride;
    C += (long long)b * Cbstride;
    const int m0 = blockIdx.y * 128;
    const int n0 = blockIdx.x * 128;

    const int tid  = threadIdx.x;
    const int wid  = tid >> 5;
    const int lane = tid & 31;
    const int wr = wid >> 2;            // 0..1 -> m offset wr*64
    const int wc = wid & 3;             // 0..3 -> n offset wc*32
    const int lr = lane >> 2;           // groupID 0..7
    const int lc = lane & 3;            // threadID-in-group 0..3

    float acc[4][4][4];
#pragma unroll
    for (int mi = 0; mi < 4; mi++)
#pragma unroll
        for (int ni = 0; ni < 4; ni++)
#pragma unroll
            for (int j = 0; j < 4; j++) acc[mi][ni][j] = 0.f;

    // A-load mapping: 128 rows x 16 k per iter; thread -> row tid>>1, 8 k's
    const int arow_ld = tid >> 1;
    const int akq     = (tid & 1) * 8;
    int mg = m0 + arow_ld; if (mg > M - 1) mg = M - 1;
    const float* Ap = A + (long long)mg * Arow;
    // B-load mapping: 16 rows x 128 n per iter; thread -> row tid>>4, 8 n's
    const int brow_ld = tid >> 4;
    const int bcol    = (tid & 15) * 8;

#pragma unroll 1
    for (int k0 = 0; k0 < K; k0 += 16) {
        float4 v0 = *reinterpret_cast<const float4*>(Ap + k0 + akq);
        float4 v1 = *reinterpret_cast<const float4*>(Ap + k0 + akq + 4);
        const float* Wp = W + (long long)(k0 + brow_ld) * 256 + n0 + bcol;
        float4 w0 = *reinterpret_cast<const float4*>(Wp);
        float4 w1 = *reinterpret_cast<const float4*>(Wp + 4);

        uint4 ua, ub;
        ua.x = f2tf(v0.x); ua.y = f2tf(v0.y); ua.z = f2tf(v0.z); ua.w = f2tf(v0.w);
        ub.x = f2tf(v1.x); ub.y = f2tf(v1.y); ub.z = f2tf(v1.z); ub.w = f2tf(v1.w);
        *reinterpret_cast<uint4*>(&As[arow_ld][akq])     = ua;
        *reinterpret_cast<uint4*>(&As[arow_ld][akq + 4]) = ub;

        ua.x = f2tf(w0.x); ua.y = f2tf(w0.y); ua.z = f2tf(w0.z); ua.w = f2tf(w0.w);
        ub.x = f2tf(w1.x); ub.y = f2tf(w1.y); ub.z = f2tf(w1.z); ub.w = f2tf(w1.w);
        *reinterpret_cast<uint4*>(&Bs[brow_ld][bcol])     = ua;
        *reinterpret_cast<uint4*>(&Bs[brow_ld][bcol + 4]) = ub;

        __syncthreads();

#pragma unroll
        for (int ks = 0; ks < 2; ks++) {
            const int kb = ks * 8;
            uint32_t af[4][4];
#pragma unroll
            for (int mi = 0; mi < 4; mi++) {
                const int mrow = wr * 64 + mi * 16 + lr;
                af[mi][0] = __float_as_uint(As[mrow][kb + lc]);
                af[mi][1] = __float_as_uint(As[mrow + 8][kb + lc]);
                af[mi][2] = __float_as_uint(As[mrow][kb + lc + 4]);
                af[mi][3] = __float_as_uint(As[mrow + 8][kb + lc + 4]);
            }
            uint32_t bf[4][2];
#pragma unroll
            for (int ni = 0; ni < 4; ni++) {
                const int ncol = wc * 32 + ni * 8 + lr;
                bf[ni][0] = __float_as_uint(Bs[kb + lc][ncol]);
                bf[ni][1] = __float_as_uint(Bs[kb + lc + 4][ncol]);
            }
#pragma unroll
            for (int mi = 0; mi < 4; mi++)
#pragma unroll
                for (int ni = 0; ni < 4; ni++)
                    mma_tf32_16x8x8(acc[mi][ni], af[mi], bf[ni]);
        }
        __syncthreads();
    }

    // ---------------- epilogue ----------------
#pragma unroll
    for (int mi = 0; mi < 4; mi++) {
        const int r0 = m0 + wr * 64 + mi * 16 + lr;
        const int r1 = r0 + 8;
#pragma unroll
        for (int ni = 0; ni < 4; ni++) {
            const int col = n0 + wc * 32 + ni * 8 + 2 * lc;
            const float b0v = bias[col], b1v = bias[col + 1];
            if (r0 < M) {
                float2 o;
                o.x = acc[mi][ni][0] + b0v;
                o.y = acc[mi][ni][1] + b1v;
                if (ACT == 1) { o.x = fmaxf(o.x, 0.f); o.y = fmaxf(o.y, 0.f); }
                *reinterpret_cast<float2*>(C + (long long)r0 * Crow + col) = o;
            }
            if (r1 < M) {
                float2 o;
                o.x = acc[mi][ni][2] + b0v;
                o.y = acc[mi][ni][3] + b1v;
                if (ACT == 1) { o.x = fmaxf(o.x, 0.f); o.y = fmaxf(o.y, 0.f); }
                *reinterpret_cast<float2*>(C + (long long)r1 * Crow + col) = o;
            }
        }
    }
}

// =====================================================================
// First gated layer (fp32 CUDA cores): input h0 (16383 rows x 256/batch).
// =====================================================================
__global__ void first_gated_k(const float* __restrict__ h0,
                              const float* __restrict__ gW, const float* __restrict__ gb,
                              const float* __restrict__ fW, const float* __restrict__ fb,
                              const float* __restrict__ sW, const float* __restrict__ sb,
                              float* __restrict__ out)
{
    const int M  = 16382;
    const int b  = blockIdx.y;
    const int m0 = blockIdx.x * 128;
    const float* A = h0 + (long long)b * 16384 * 256;

    __shared__ __align__(16) float As[8][128];
    __shared__ __align__(16) float Bs[8][48];
    __shared__ float P[128][25];

    const int tid = threadIdx.x;
    const int tr  = tid >> 3;
    const int tc  = tid & 7;
    const int arow = tid >> 1;
    const int akq  = (tid & 1) * 4;

    int mload = m0 + arow; if (mload > M - 1) mload = M - 1;
    const float* Ap = A + (long long)mload * 256;

    float accG[4][3], accF[4][3];
#pragma unroll
    for (int i = 0; i < 4; i++)
#pragma unroll
        for (int j = 0; j < 3; j++) { accG[i][j] = 0.f; accF[i][j] = 0.f; }

    for (int k0 = 0; k0 < 512; k0 += 8) {
        float4 av = *reinterpret_cast<const float4*>(Ap + k0 + akq);
        As[akq + 0][arow] = av.x;
        As[akq + 1][arow] = av.y;
        As[akq + 2][arow] = av.z;
        As[akq + 3][arow] = av.w;
        if (tid < 96) {
            int kk = tid / 12, n = (tid % 12) * 4;
            const float* srcp = (n < 24) ? (gW + (long long)(k0 + kk) * 24 + n)
                                         : (fW + (long long)(k0 + kk) * 24 + (n - 24));
            *reinterpret_cast<float4*>(&Bs[kk][n]) = *reinterpret_cast<const float4*>(srcp);
        }
        __syncthreads();
#pragma unroll
        for (int k = 0; k < 8; k++) {
            float a[4];
            *reinterpret_cast<float4*>(a) = *reinterpret_cast<const float4*>(&As[k][tr * 4]);
            float wg[3], wf[3];
#pragma unroll
            for (int j = 0; j < 3; j++) { wg[j] = Bs[k][tc * 3 + j]; wf[j] = Bs[k][24 + tc * 3 + j]; }
#pragma unroll
            for (int i = 0; i < 4; i++)
#pragma unroll
                for (int j = 0; j < 3; j++) {
                    accG[i][j] += a[i] * wg[j];
                    accF[i][j] += a[i] * wf[j];
                }
        }
        __syncthreads();
    }

#pragma unroll
    for (int i = 0; i < 4; i++)
#pragma unroll
        for (int j = 0; j < 3; j++) {
            float g = accG[i][j] + gb[tc * 3 + j];
            float f = accF[i][j] + fb[tc * 3 + j];
            P[tr * 4 + i][tc * 3 + j] = tanhf(f) / (1.f + expf(-g));
        }
    __syncthreads();

    float acc2[4][3];
#pragma unroll
    for (int i = 0; i < 4; i++)
#pragma unroll
        for (int j = 0; j < 3; j++) acc2[i][j] = 0.f;
#pragma unroll
    for (int k = 0; k < 24; k++) {
        float a[4];
#pragma unroll
        for (int i = 0; i < 4; i++) a[i] = P[tr * 4 + i][k];
        float w0 = sW[k * 24 + tc * 3 + 0];
        float w1 = sW[k * 24 + tc * 3 + 1];
        float w2 = sW[k * 24 + tc * 3 + 2];
#pragma unroll
        for (int i = 0; i < 4; i++) {
            acc2[i][0] += a[i] * w0;
            acc2[i][1] += a[i] * w1;
            acc2[i][2] += a[i] * w2;
        }
    }
    float* O = out + (long long)b * 16384 * 24;
#pragma unroll
    for (int i = 0; i < 4; i++) {
        int m = m0 + tr * 4 + i;
        if (m < M) {
#pragma unroll
            for (int j = 0; j < 3; j++)
                O[(long long)m * 24 + tc * 3 + j] = acc2[i][j] + sb[tc * 3 + j];
        }
    }
}

// =====================================================================
// Dilated gated 24-ch layer (fp32 CUDA cores).
// =====================================================================
__global__ void gated24_k(const float* __restrict__ in, float* __restrict__ out,
                          int Lin, int Lout, int d,
                          const float* __restrict__ gW, const float* __restrict__ gb,
                          const float* __restrict__ fW, const float* __restrict__ fb,
                          const float* __restrict__ sW, const float* __restrict__ sb)
{
    const int b  = blockIdx.y;
    const int m0 = blockIdx.x * 128;
    const float* Ab = in + (long long)b * 16384 * 24;

    __shared__ float As[48][129];
    __shared__ float Wc[48][48];
    __shared__ float P[128][25];

    const int tid = threadIdx.x;

    for (int i = tid; i < 2304; i += 256) {
        int j48 = i / 48, c48 = i % 48;
        int k = j48 / 24, j = j48 % 24;
        Wc[j48][c48] = (c48 < 24) ? gW[(k * 24 + j) * 24 + c48]
                                  : fW[(k * 24 + j) * 24 + (c48 - 24)];
    }

    int lim0 = (Lin - m0) * 24;       if (lim0 > 3072) lim0 = 3072;
    int lim1 = (Lin - m0 - d) * 24;   if (lim1 > 3072) lim1 = 3072; if (lim1 < 0) lim1 = 0;
    const float* s0 = Ab + (long long)m0 * 24;
    const float* s1 = s0 + (long long)d * 24;
    for (int i = tid; i < 3072; i += 256) {
        int t = i / 24, j = i % 24;
        As[j][t]      = (i < lim0) ? s0[i] : 0.f;
        As[24 + j][t] = (i < lim1) ? s1[i] : 0.f;
    }
    __syncthreads();

    const int tr = tid >> 3;
    const int tc = tid & 7;

    float accG[4][3], accF[4][3];
#pragma unroll
    for (int i = 0; i < 4; i++)
#pragma unroll
        for (int j = 0; j < 3; j++) { accG[i][j] = 0.f; accF[i][j] = 0.f; }

#pragma unroll
    for (int k = 0; k < 48; k++) {
        float a[4];
#pragma unroll
        for (int i = 0; i < 4; i++) a[i] = As[k][tr * 4 + i];
        float wg[3], wf[3];
#pragma unroll
        for (int j = 0; j < 3; j++) { wg[j] = Wc[k][tc * 3 + j]; wf[j] = Wc[k][24 + tc * 3 + j]; }
#pragma unroll
        for (int i = 0; i < 4; i++)
#pragma unroll
            for (int j = 0; j < 3; j++) {
                accG[i][j] += a[i] * wg[j];
                accF[i][j] += a[i] * wf[j];
            }
    }

#pragma unroll
    for (int i = 0; i < 4; i++)
#pragma unroll
        for (int j = 0; j < 3; j++) {
            float g = accG[i][j] + gb[tc * 3 + j];
            float f = accF[i][j] + fb[tc * 3 + j];
            P[tr * 4 + i][tc * 3 + j] = tanhf(f) / (1.f + expf(-g));
        }
    __syncthreads();

    float acc2[4][3];
#pragma unroll
    for (int i = 0; i < 4; i++)
#pragma unroll
        for (int j = 0; j < 3; j++) acc2[i][j] = 0.f;
#pragma unroll
    for (int k = 0; k < 24; k++) {
        float a[4];
#pragma unroll
        for (int i = 0; i < 4; i++) a[i] = P[tr * 4 + i][k];
        float w0 = sW[k * 24 + tc * 3 + 0];
        float w1 = sW[k * 24 + tc * 3 + 1];
        float w2 = sW[k * 24 + tc * 3 + 2];
#pragma unroll
        for (int i = 0; i < 4; i++) {
            acc2[i][0] += a[i] * w0;
            acc2[i][1] += a[i] * w1;
            acc2[i][2] += a[i] * w2;
        }
    }
    float* O = out + (long long)b * 16384 * 24;
#pragma unroll
    for (int i = 0; i < 4; i++) {
        int m = m0 + tr * 4 + i;
        if (m < Lout) {
#pragma unroll
            for (int j = 0; j < 3; j++)
                O[(long long)m * 24 + tc * 3 + j] = acc2[i][j] + sb[tc * 3 + j];
        }
    }
}

// =====================================================================
// Residual + ReLU:  a[t, c] = relu( (prev[t+256] + cur[t]) x R(24x128) + rb )
// =====================================================================
__global__ void res_relu_k(const float* __restrict__ prev, const float* __restrict__ cur,
                           const float* __restrict__ R, const float* __restrict__ rb,
                           float* __restrict__ outa)
{
    const int b  = blockIdx.y;
    const int m0 = blockIdx.x * 128;
    const float* Pp = prev + (long long)b * 16384 * 24 + (long long)(m0 + 256) * 24;
    const float* Cp = cur  + (long long)b * 16384 * 24 + (long long)m0 * 24;

    __shared__ float As[24][129];
    __shared__ __align__(16) float Bs[24][128];

    const int tid = threadIdx.x;
    for (int i = tid; i < 3072; i += 256) {
        int t = i / 24, j = i % 24;
        As[j][t] = Pp[i] + Cp[i];
    }
    for (int i = tid; i < 3072; i += 256) Bs[i >> 7][i & 127] = R[i];
    __syncthreads();

    const int tr = tid >> 4, tc = tid & 15;
    float acc[8][8];
#pragma unroll
    for (int i = 0; i < 8; i++)
#pragma unroll
        for (int j = 0; j < 8; j++) acc[i][j] = 0.f;

#pragma unroll
    for (int k = 0; k < 24; k++) {
        float a[8], w[8];
#pragma unroll
        for (int i = 0; i < 8; i++) a[i] = As[k][tr * 8 + i];
        *reinterpret_cast<float4*>(w)     = *reinterpret_cast<const float4*>(&Bs[k][tc * 8]);
        *reinterpret_cast<float4*>(w + 4) = *reinterpret_cast<const float4*>(&Bs[k][tc * 8 + 4]);
#pragma unroll
        for (int i = 0; i < 8; i++)
#pragma unroll
            for (int j = 0; j < 8; j++) acc[i][j] += a[i] * w[j];
    }

    float* O = outa + (long long)b * 15360 * 128 + (long long)m0 * 128;
#pragma unroll
    for (int i = 0; i < 8; i++)
#pragma unroll
        for (int j = 0; j < 8; j++)
            O[(long long)(tr * 8 + i) * 128 + tc * 8 + j] = fmaxf(acc[i][j] + rb[tc * 8 + j], 0.f);
}

// =====================================================================
// In-place softmax over 256 channels; one block per row.
// =====================================================================
__global__ void softmax256_k(float* __restrict__ io)
{
    float* p = io + (long long)blockIdx.x * 256;
    const int tid = threadIdx.x;
    __shared__ float red[8];
    __shared__ float bval;

    float v = p[tid];
    float m = v;
#pragma unroll
    for (int o = 16; o; o >>= 1) m = fmaxf(m, __shfl_xor_sync(0xffffffffu, m, o));
    if ((tid & 31) == 0) red[tid >> 5] = m;
    __syncthreads();
    if (tid == 0) {
        float t = red[0];
#pragma unroll
        for (int i = 1; i < 8; i++) t = fmaxf(t, red[i]);
        bval = t;
    }
    __syncthreads();
    m = bval;
    float e = expf(v - m);
    float s = e;
#pragma unroll
    for (int o = 16; o; o >>= 1) s += __shfl_xor_sync(0xffffffffu, s, o);
    if ((tid & 31) == 0) red[tid >> 5] = s;
    __syncthreads();
    if (tid == 0) {
        float t = 0.f;
#pragma unroll
        for (int i = 0; i < 8; i++) t += red[i];
        bval = t;
    }
    __syncthreads();
    p[tid] = e / bval;
}

// =====================================================================
extern "C" void kernel_launch(void* const* d_in, const int* in_sizes, int n_in,
                              void* d_out, int out_size)
{
    const float* x        = (const float*)d_in[0];
    const float* causal_W = (const float*)d_in[1];
    const float* causal_b = (const float*)d_in[2];
    const float* gW0      = (const float*)d_in[3];
    const float* gb0      = (const float*)d_in[4];
    const float* fW0      = (const float*)d_in[5];
    const float* fb0      = (const float*)d_in[6];
    const float* sW0      = (const float*)d_in[7];
    const float* sb0      = (const float*)d_in[8];
    const float* gate_W   = (const float*)d_in[9];
    const float* gate_b   = (const float*)d_in[10];
    const float* filter_W = (const float*)d_in[11];
    const float* filter_b = (const float*)d_in[12];
    const float* scale_W  = (const float*)d_in[13];
    const float* scale_b  = (const float*)d_in[14];
    const float* res_W    = (const float*)d_in[15];
    const float* res_b    = (const float*)d_in[16];
    const float* f1_W     = (const float*)d_in[17];
    const float* f1_b     = (const float*)d_in[18];
    const float* f2_W     = (const float*)d_in[19];
    const float* f2_b     = (const float*)d_in[20];
    float* out = (float*)d_out;

    float *h0, *p0, *p1, *accb, *a2b;
    cudaGetSymbolAddress((void**)&h0,   g_h0);
    cudaGetSymbolAddress((void**)&p0,   g_p0);
    cudaGetSymbolAddress((void**)&p1,   g_p1);
    cudaGetSymbolAddress((void**)&accb, g_accb);
    cudaGetSymbolAddress((void**)&a2b,  g_a2);

    // 1) causal conv as tf32 mma GEMM: per-batch M=16383, K=512, N=256
    mma_gemm_k<0><<<dim3(2, 128, 8), 256>>>(x, 16384LL * 256, 16383, 512, 256,
                                            causal_W, causal_b, h0, 16384LL * 256, 256);

    // 2) first gated layer -> p0 (16382 rows/batch)
    first_gated_k<<<dim3(128, 8), 256>>>(h0, gW0, gb0, fW0, fb0, sW0, sb0, p0);

    // 3) nine dilated gated layers (only last residual matters)
    float* bufs[2] = { p0, p1 };
    int cur = 0;
    int Lin = 16382;
    for (int i = 0; i < 9; i++) {
        int d = 2 << i;
        int Lout = Lin - d;
        gated24_k<<<dim3((Lout + 127) / 128, 8), 256>>>(
            bufs[cur], bufs[1 - cur], Lin, Lout, d,
            gate_W + i * 1152, gate_b + i * 24,
            filter_W + i * 1152, filter_b + i * 24,
            scale_W + i * 576, scale_b + i * 24);
        cur ^= 1;
        Lin = Lout;
    }

    // 4) residual combine + res conv (i=8 only) + ReLU -> accb (15360 x 128)
    res_relu_k<<<dim3(120, 8), 256>>>(bufs[1 - cur], bufs[cur],
                                      res_W + 8 * 24 * 128, res_b + 8 * 128, accb);

    // 5) f1: tf32 mma GEMM K=128 + ReLU -> a2b (122880 x 256)
    mma_gemm_k<1><<<dim3(2, 960, 1), 256>>>(accb, 0, 122880, 128, 128,
                                            f1_W, f1_b, a2b, 0, 256);

    // 6) f2: tf32 mma GEMM K=256 -> logits in d_out
    mma_gemm_k<0><<<dim3(2, 960, 1), 256>>>(a2b, 0, 122880, 256, 256,
                                            f2_W, f2_b, out, 0, 256);

    // 7) softmax over channels, in place
    softmax256_k<<<122880, 256>>>(out);
}

// round 7
// speedup vs baseline: 2.0727x; 1.2374x over previous
#include <cuda_runtime.h>
#include <cstdint>
#include <math.h>

// ---------------- scratch (device globals; no allocation allowed) ----------------
__device__ float g_h0[33554432];          // 8*16384*256  (causal output)
__device__ float g_p0[3145728];           // 8*16384*24   ping
__device__ float g_p1[3145728];           // 8*16384*24   pong
__device__ float g_accb[15728640];        // 8*15360*128  relu(res conv)
__device__ float g_a2[31457280];          // 8*15360*256  relu(f1)

__device__ __forceinline__ uint32_t smem_u32(const void* p) {
    uint32_t a;
    asm("{ .reg .u64 t; cvta.to.shared.u64 t, %1; cvt.u32.u64 %0, t; }" : "=r"(a) : "l"(p));
    return a;
}
__device__ __forceinline__ void cpa16(const void* smem_dst, const void* gsrc) {
    uint32_t a = smem_u32(smem_dst);
    asm volatile("cp.async.cg.shared.global [%0], [%1], 16;" :: "r"(a), "l"(gsrc) : "memory");
}
#define CP_COMMIT() asm volatile("cp.async.commit_group;" ::: "memory")
#define CP_WAIT0()  asm volatile("cp.async.wait_group 0;" ::: "memory")
#define CP_WAIT1()  asm volatile("cp.async.wait_group 1;" ::: "memory")

__device__ __forceinline__ void mma_tf32_16x8x8(float c[4],
                                                const uint32_t a[4], const uint32_t b[2])
{
    asm volatile(
        "mma.sync.aligned.m16n8k8.row.col.f32.tf32.tf32.f32 "
        "{%0,%1,%2,%3}, {%4,%5,%6,%7}, {%8,%9}, {%0,%1,%2,%3};"
        : "+f"(c[0]), "+f"(c[1]), "+f"(c[2]), "+f"(c[3])
        : "r"(a[0]), "r"(a[1]), "r"(a[2]), "r"(a[3]), "r"(b[0]), "r"(b[1]));
}

// =====================================================================
// tf32 mma.sync GEMM w/ cp.async 2-stage pipeline.
// C[m, n] = act( A[m..] (K contiguous from row base, row stride Arow)
//                x W[K,256] + bias ), N=256 via grid.x=2 tiles of 128.
// BM=128, BN=128, BK=16, 256 threads (8 warps, 2x4), warp tile 64x32.
// =====================================================================
template<int ACT>
__global__ void __launch_bounds__(256)
mma_gemm_k(const float* __restrict__ A, long long Abstride,
           int M, int K, int Arow,
           const float* __restrict__ W, const float* __restrict__ bias,
           float* __restrict__ C, long long Cbstride, int Crow)
{
    __shared__ __align__(16) float As[2][128][20];
    __shared__ __align__(16) float Bs[2][16][136];

    const int b = blockIdx.z;
    A += (long long)b * Abstride;
    C += (long long)b * Cbstride;
    const int m0 = blockIdx.y * 128;
    const int n0 = blockIdx.x * 128;

    const int tid  = threadIdx.x;
    const int wid  = tid >> 5;
    const int lane = tid & 31;
    const int wr = wid >> 2;
    const int wc = wid & 3;
    const int lr = lane >> 2;
    const int lc = lane & 3;

    float acc[4][4][4];
#pragma unroll
    for (int mi = 0; mi < 4; mi++)
#pragma unroll
        for (int ni = 0; ni < 4; ni++)
#pragma unroll
            for (int j = 0; j < 4; j++) acc[mi][ni][j] = 0.f;

    const int arow_ld = tid >> 1;
    const int akq     = (tid & 1) * 8;
    int mg = m0 + arow_ld; if (mg > M - 1) mg = M - 1;
    const float* Ap = A + (long long)mg * Arow;
    const int brow_ld = tid >> 4;
    const int bcol    = (tid & 15) * 8;

    const int nch = K >> 4;

    // prefetch chunk 0
    {
        cpa16(&As[0][arow_ld][akq],     Ap + akq);
        cpa16(&As[0][arow_ld][akq + 4], Ap + akq + 4);
        const float* Wp = W + (long long)brow_ld * 256 + n0 + bcol;
        cpa16(&Bs[0][brow_ld][bcol],     Wp);
        cpa16(&Bs[0][brow_ld][bcol + 4], Wp + 4);
        CP_COMMIT();
    }

#pragma unroll 1
    for (int ic = 0; ic < nch; ic++) {
        const int s = ic & 1;
        if (ic + 1 < nch) {
            const int k1 = (ic + 1) << 4;
            cpa16(&As[s ^ 1][arow_ld][akq],     Ap + k1 + akq);
            cpa16(&As[s ^ 1][arow_ld][akq + 4], Ap + k1 + akq + 4);
            const float* Wp = W + (long long)(k1 + brow_ld) * 256 + n0 + bcol;
            cpa16(&Bs[s ^ 1][brow_ld][bcol],     Wp);
            cpa16(&Bs[s ^ 1][brow_ld][bcol + 4], Wp + 4);
            CP_COMMIT();
            CP_WAIT1();
        } else {
            CP_WAIT0();
        }
        __syncthreads();

#pragma unroll
        for (int ks = 0; ks < 2; ks++) {
            const int kb = ks * 8;
            uint32_t af[4][4];
#pragma unroll
            for (int mi = 0; mi < 4; mi++) {
                const int mrow = wr * 64 + mi * 16 + lr;
                af[mi][0] = __float_as_uint(As[s][mrow][kb + lc]);
                af[mi][1] = __float_as_uint(As[s][mrow + 8][kb + lc]);
                af[mi][2] = __float_as_uint(As[s][mrow][kb + lc + 4]);
                af[mi][3] = __float_as_uint(As[s][mrow + 8][kb + lc + 4]);
            }
            uint32_t bf[4][2];
#pragma unroll
            for (int ni = 0; ni < 4; ni++) {
                const int ncol = wc * 32 + ni * 8 + lr;
                bf[ni][0] = __float_as_uint(Bs[s][kb + lc][ncol]);
                bf[ni][1] = __float_as_uint(Bs[s][kb + lc + 4][ncol]);
            }
#pragma unroll
            for (int mi = 0; mi < 4; mi++)
#pragma unroll
                for (int ni = 0; ni < 4; ni++)
                    mma_tf32_16x8x8(acc[mi][ni], af[mi], bf[ni]);
        }
        __syncthreads();
    }

    // ---------------- epilogue ----------------
#pragma unroll
    for (int mi = 0; mi < 4; mi++) {
        const int r0 = m0 + wr * 64 + mi * 16 + lr;
        const int r1 = r0 + 8;
#pragma unroll
        for (int ni = 0; ni < 4; ni++) {
            const int col = n0 + wc * 32 + ni * 8 + 2 * lc;
            const float b0v = bias[col], b1v = bias[col + 1];
            if (r0 < M) {
                float2 o;
                o.x = acc[mi][ni][0] + b0v;
                o.y = acc[mi][ni][1] + b1v;
                if (ACT == 1) { o.x = fmaxf(o.x, 0.f); o.y = fmaxf(o.y, 0.f); }
                *reinterpret_cast<float2*>(C + (long long)r0 * Crow + col) = o;
            }
            if (r1 < M) {
                float2 o;
                o.x = acc[mi][ni][2] + b0v;
                o.y = acc[mi][ni][3] + b1v;
                if (ACT == 1) { o.x = fmaxf(o.x, 0.f); o.y = fmaxf(o.y, 0.f); }
                *reinterpret_cast<float2*>(C + (long long)r1 * Crow + col) = o;
            }
        }
    }
}

// =====================================================================
// Dilated gated 24-ch layer, tensorized.
// Stage1: [128 x 48] = A[128 x 48] x Wc[48 x 48]  (gate | filter fused)
// act: p = tanh(f+fb) * sigmoid(g+gb) -> P[128][24]
// Stage2: out = P x sW[24 x 24] + sb
// 256 threads = 8 warps, each warp owns 16 rows (m16n8k8 tiles).
// =====================================================================
__global__ void __launch_bounds__(256)
gated24_mma_k(const float* __restrict__ in, float* __restrict__ out,
              int Lin, int Lout, int d,
              const float* __restrict__ gW, const float* __restrict__ gb,
              const float* __restrict__ fW, const float* __restrict__ fb,
              const float* __restrict__ sW, const float* __restrict__ sb)
{
    __shared__ __align__(16) float As[128][52];
    __shared__ float Wc[48][56];
    __shared__ float W2[24][56];
    float* P = &As[0][0];          // [128][28] alias, used after stage1

    const int b  = blockIdx.y;
    const int m0 = blockIdx.x * 128;
    const float* Ab = in + (long long)b * 16384 * 24;

    const int tid = threadIdx.x;
    const int wid = tid >> 5;
    const int lane = tid & 31;
    const int lr = lane >> 2;
    const int lc = lane & 3;
    const int mrow = wid * 16;

    for (int i = tid; i < 2304; i += 256) {
        int k = i / 48, n = i % 48;
        Wc[k][n] = (n < 24) ? gW[k * 24 + n] : fW[k * 24 + (n - 24)];
    }
    for (int i = tid; i < 576; i += 256) W2[i / 24][i % 24] = sW[i];

    int lim0 = (Lin - m0) * 24;       if (lim0 > 3072) lim0 = 3072;
    int lim1 = (Lin - m0 - d) * 24;   if (lim1 > 3072) lim1 = 3072; if (lim1 < 0) lim1 = 0;
    const float* s0 = Ab + (long long)m0 * 24;
    const float* s1 = s0 + (long long)d * 24;
    for (int i = tid; i < 3072; i += 256) {
        int t = i / 24, j = i % 24;
        As[t][j]      = (i < lim0) ? s0[i] : 0.f;
        As[t][24 + j] = (i < lim1) ? s1[i] : 0.f;
    }
    __syncthreads();

    float acc[6][4];
#pragma unroll
    for (int ni = 0; ni < 6; ni++)
#pragma unroll
        for (int j = 0; j < 4; j++) acc[ni][j] = 0.f;

#pragma unroll
    for (int ks = 0; ks < 6; ks++) {
        const int kb = ks * 8;
        uint32_t a[4];
        a[0] = __float_as_uint(As[mrow + lr][kb + lc]);
        a[1] = __float_as_uint(As[mrow + lr + 8][kb + lc]);
        a[2] = __float_as_uint(As[mrow + lr][kb + lc + 4]);
        a[3] = __float_as_uint(As[mrow + lr + 8][kb + lc + 4]);
#pragma unroll
        for (int ni = 0; ni < 6; ni++) {
            uint32_t bf[2];
            bf[0] = __float_as_uint(Wc[kb + lc][ni * 8 + lr]);
            bf[1] = __float_as_uint(Wc[kb + lc + 4][ni * 8 + lr]);
            mma_tf32_16x8x8(acc[ni], a, bf);
        }
    }
    __syncthreads();   // all As reads done before P alias writes

#pragma unroll
    for (int ni = 0; ni < 3; ni++) {
        const int col = ni * 8 + 2 * lc;
#pragma unroll
        for (int j = 0; j < 4; j++) {
            const int c = col + (j & 1);
            float g = acc[ni][j]     + gb[c];
            float f = acc[ni + 3][j] + fb[c];
            float p = tanhf(f) * (1.f / (1.f + __expf(-g)));
            const int m = mrow + lr + ((j >> 1) << 3);
            P[m * 28 + c] = p;
        }
    }
    __syncthreads();

    float acc2[3][4];
#pragma unroll
    for (int ni = 0; ni < 3; ni++)
#pragma unroll
        for (int j = 0; j < 4; j++) acc2[ni][j] = 0.f;

#pragma unroll
    for (int ks = 0; ks < 3; ks++) {
        const int kb = ks * 8;
        uint32_t a[4];
        a[0] = __float_as_uint(P[(mrow + lr) * 28 + kb + lc]);
        a[1] = __float_as_uint(P[(mrow + lr + 8) * 28 + kb + lc]);
        a[2] = __float_as_uint(P[(mrow + lr) * 28 + kb + lc + 4]);
        a[3] = __float_as_uint(P[(mrow + lr + 8) * 28 + kb + lc + 4]);
#pragma unroll
        for (int ni = 0; ni < 3; ni++) {
            uint32_t bf[2];
            bf[0] = __float_as_uint(W2[kb + lc][ni * 8 + lr]);
            bf[1] = __float_as_uint(W2[kb + lc + 4][ni * 8 + lr]);
            mma_tf32_16x8x8(acc2[ni], a, bf);
        }
    }

    float* O = out + (long long)b * 16384 * 24;
    const int r0 = m0 + mrow + lr;
    const int r1 = r0 + 8;
#pragma unroll
    for (int ni = 0; ni < 3; ni++) {
        const int col = ni * 8 + 2 * lc;
        if (r0 < Lout) {
            float2 o = { acc2[ni][0] + sb[col], acc2[ni][1] + sb[col + 1] };
            *reinterpret_cast<float2*>(O + (long long)r0 * 24 + col) = o;
        }
        if (r1 < Lout) {
            float2 o = { acc2[ni][2] + sb[col], acc2[ni][3] + sb[col + 1] };
            *reinterpret_cast<float2*>(O + (long long)r1 * 24 + col) = o;
        }
    }
}

// =====================================================================
// First gated layer, tensorized + cp.async pipelined over K=512.
// A row = 512 contiguous floats (h0[t] ++ h0[t+1]).
// =====================================================================
__global__ void __launch_bounds__(256)
first_gated_mma_k(const float* __restrict__ h0,
                  const float* __restrict__ gW, const float* __restrict__ gb,
                  const float* __restrict__ fW, const float* __restrict__ fb,
                  const float* __restrict__ sW, const float* __restrict__ sb,
                  float* __restrict__ out)
{
    __shared__ __align__(16) float As[2][128][20];
    __shared__ float Bs[2][16][56];
    __shared__ float W2[24][56];
    float* P = &As[0][0][0];       // [128][28] alias after mainloop

    const int M  = 16382;
    const int b  = blockIdx.y;
    const int m0 = blockIdx.x * 128;
    const float* A = h0 + (long long)b * 16384 * 256;

    const int tid = threadIdx.x;
    const int wid = tid >> 5;
    const int lane = tid & 31;
    const int lr = lane >> 2;
    const int lc = lane & 3;
    const int mrow = wid * 16;

    const int arow_ld = tid >> 1;
    const int akq     = (tid & 1) * 8;
    int mg = m0 + arow_ld; if (mg > M - 1) mg = M - 1;
    const float* Ap = A + (long long)mg * 256;

    for (int i = tid; i < 576; i += 256) W2[i / 24][i % 24] = sW[i];

    // prefetch chunk 0
    for (int i = tid; i < 768; i += 256) {
        int kk = i / 48, n = i % 48;
        Bs[0][kk][n] = (n < 24) ? gW[kk * 24 + n] : fW[kk * 24 + (n - 24)];
    }
    cpa16(&As[0][arow_ld][akq],     Ap + akq);
    cpa16(&As[0][arow_ld][akq + 4], Ap + akq + 4);
    CP_COMMIT();

    float acc[6][4];
#pragma unroll
    for (int ni = 0; ni < 6; ni++)
#pragma unroll
        for (int j = 0; j < 4; j++) acc[ni][j] = 0.f;

#pragma unroll 1
    for (int ic = 0; ic < 32; ic++) {
        const int s = ic & 1;
        if (ic < 31) {
            const int k1 = (ic + 1) * 16;
            for (int i = tid; i < 768; i += 256) {
                int kk = i / 48, n = i % 48;
                Bs[s ^ 1][kk][n] = (n < 24) ? gW[(k1 + kk) * 24 + n]
                                            : fW[(k1 + kk) * 24 + (n - 24)];
            }
            cpa16(&As[s ^ 1][arow_ld][akq],     Ap + k1 + akq);
            cpa16(&As[s ^ 1][arow_ld][akq + 4], Ap + k1 + akq + 4);
            CP_COMMIT();
            CP_WAIT1();
        } else {
            CP_WAIT0();
        }
        __syncthreads();

#pragma unroll
        for (int ks = 0; ks < 2; ks++) {
            const int kb = ks * 8;
            uint32_t a[4];
            a[0] = __float_as_uint(As[s][mrow + lr][kb + lc]);
            a[1] = __float_as_uint(As[s][mrow + lr + 8][kb + lc]);
            a[2] = __float_as_uint(As[s][mrow + lr][kb + lc + 4]);
            a[3] = __float_as_uint(As[s][mrow + lr + 8][kb + lc + 4]);
#pragma unroll
            for (int ni = 0; ni < 6; ni++) {
                uint32_t bf[2];
                bf[0] = __float_as_uint(Bs[s][kb + lc][ni * 8 + lr]);
                bf[1] = __float_as_uint(Bs[s][kb + lc + 4][ni * 8 + lr]);
                mma_tf32_16x8x8(acc[ni], a, bf);
            }
        }
        __syncthreads();
    }

#pragma unroll
    for (int ni = 0; ni < 3; ni++) {
        const int col = ni * 8 + 2 * lc;
#pragma unroll
        for (int j = 0; j < 4; j++) {
            const int c = col + (j & 1);
            float g = acc[ni][j]     + gb[c];
            float f = acc[ni + 3][j] + fb[c];
            float p = tanhf(f) * (1.f / (1.f + __expf(-g)));
            const int m = mrow + lr + ((j >> 1) << 3);
            P[m * 28 + c] = p;
        }
    }
    __syncthreads();

    float acc2[3][4];
#pragma unroll
    for (int ni = 0; ni < 3; ni++)
#pragma unroll
        for (int j = 0; j < 4; j++) acc2[ni][j] = 0.f;

#pragma unroll
    for (int ks = 0; ks < 3; ks++) {
        const int kb = ks * 8;
        uint32_t a[4];
        a[0] = __float_as_uint(P[(mrow + lr) * 28 + kb + lc]);
        a[1] = __float_as_uint(P[(mrow + lr + 8) * 28 + kb + lc]);
        a[2] = __float_as_uint(P[(mrow + lr) * 28 + kb + lc + 4]);
        a[3] = __float_as_uint(P[(mrow + lr + 8) * 28 + kb + lc + 4]);
#pragma unroll
        for (int ni = 0; ni < 3; ni++) {
            uint32_t bf[2];
            bf[0] = __float_as_uint(W2[kb + lc][ni * 8 + lr]);
            bf[1] = __float_as_uint(W2[kb + lc + 4][ni * 8 + lr]);
            mma_tf32_16x8x8(acc2[ni], a, bf);
        }
    }

    float* O = out + (long long)b * 16384 * 24;
    const int r0 = m0 + mrow + lr;
    const int r1 = r0 + 8;
#pragma unroll
    for (int ni = 0; ni < 3; ni++) {
        const int col = ni * 8 + 2 * lc;
        if (r0 < M) {
            float2 o = { acc2[ni][0] + sb[col], acc2[ni][1] + sb[col + 1] };
            *reinterpret_cast<float2*>(O + (long long)r0 * 24 + col) = o;
        }
        if (r1 < M) {
            float2 o = { acc2[ni][2] + sb[col], acc2[ni][3] + sb[col + 1] };
            *reinterpret_cast<float2*>(O + (long long)r1 * 24 + col) = o;
        }
    }
}

// =====================================================================
// Residual + ReLU:  a[t, c] = relu( (prev[t+256] + cur[t]) x R(24x128) + rb )
// =====================================================================
__global__ void res_relu_k(const float* __restrict__ prev, const float* __restrict__ cur,
                           const float* __restrict__ R, const float* __restrict__ rb,
                           float* __restrict__ outa)
{
    const int b  = blockIdx.y;
    const int m0 = blockIdx.x * 128;
    const float* Pp = prev + (long long)b * 16384 * 24 + (long long)(m0 + 256) * 24;
    const float* Cp = cur  + (long long)b * 16384 * 24 + (long long)m0 * 24;

    __shared__ float As[24][129];
    __shared__ __align__(16) float Bs[24][128];

    const int tid = threadIdx.x;
    for (int i = tid; i < 3072; i += 256) {
        int t = i / 24, j = i % 24;
        As[j][t] = Pp[i] + Cp[i];
    }
    for (int i = tid; i < 3072; i += 256) Bs[i >> 7][i & 127] = R[i];
    __syncthreads();

    const int tr = tid >> 4, tc = tid & 15;
    float acc[8][8];
#pragma unroll
    for (int i = 0; i < 8; i++)
#pragma unroll
        for (int j = 0; j < 8; j++) acc[i][j] = 0.f;

#pragma unroll
    for (int k = 0; k < 24; k++) {
        float a[8], w[8];
#pragma unroll
        for (int i = 0; i < 8; i++) a[i] = As[k][tr * 8 + i];
        *reinterpret_cast<float4*>(w)     = *reinterpret_cast<const float4*>(&Bs[k][tc * 8]);
        *reinterpret_cast<float4*>(w + 4) = *reinterpret_cast<const float4*>(&Bs[k][tc * 8 + 4]);
#pragma unroll
        for (int i = 0; i < 8; i++)
#pragma unroll
            for (int j = 0; j < 8; j++) acc[i][j] += a[i] * w[j];
    }

    float* O = outa + (long long)b * 15360 * 128 + (long long)m0 * 128;
#pragma unroll
    for (int i = 0; i < 8; i++)
#pragma unroll
        for (int j = 0; j < 8; j++)
            O[(long long)(tr * 8 + i) * 128 + tc * 8 + j] = fmaxf(acc[i][j] + rb[tc * 8 + j], 0.f);
}

// =====================================================================
// In-place softmax over 256 channels; one block per row.
// =====================================================================
__global__ void softmax256_k(float* __restrict__ io)
{
    float* p = io + (long long)blockIdx.x * 256;
    const int tid = threadIdx.x;
    __shared__ float red[8];
    __shared__ float bval;

    float v = p[tid];
    float m = v;
#pragma unroll
    for (int o = 16; o; o >>= 1) m = fmaxf(m, __shfl_xor_sync(0xffffffffu, m, o));
    if ((tid & 31) == 0) red[tid >> 5] = m;
    __syncthreads();
    if (tid == 0) {
        float t = red[0];
#pragma unroll
        for (int i = 1; i < 8; i++) t = fmaxf(t, red[i]);
        bval = t;
    }
    __syncthreads();
    m = bval;
    float e = expf(v - m);
    float s = e;
#pragma unroll
    for (int o = 16; o; o >>= 1) s += __shfl_xor_sync(0xffffffffu, s, o);
    if ((tid & 31) == 0) red[tid >> 5] = s;
    __syncthreads();
    if (tid == 0) {
        float t = 0.f;
#pragma unroll
        for (int i = 0; i < 8; i++) t += red[i];
        bval = t;
    }
    __syncthreads();
    p[tid] = e / bval;
}

// =====================================================================
extern "C" void kernel_launch(void* const* d_in, const int* in_sizes, int n_in,
                              void* d_out, int out_size)
{
    const float* x        = (const float*)d_in[0];
    const float* causal_W = (const float*)d_in[1];
    const float* causal_b = (const float*)d_in[2];
    const float* gW0      = (const float*)d_in[3];
    const float* gb0      = (const float*)d_in[4];
    const float* fW0      = (const float*)d_in[5];
    const float* fb0      = (const float*)d_in[6];
    const float* sW0      = (const float*)d_in[7];
    const float* sb0      = (const float*)d_in[8];
    const float* gate_W   = (const float*)d_in[9];
    const float* gate_b   = (const float*)d_in[10];
    const float* filter_W = (const float*)d_in[11];
    const float* filter_b = (const float*)d_in[12];
    const float* scale_W  = (const float*)d_in[13];
    const float* scale_b  = (const float*)d_in[14];
    const float* res_W    = (const float*)d_in[15];
    const float* res_b    = (const float*)d_in[16];
    const float* f1_W     = (const float*)d_in[17];
    const float* f1_b     = (const float*)d_in[18];
    const float* f2_W     = (const float*)d_in[19];
    const float* f2_b     = (const float*)d_in[20];
    float* out = (float*)d_out;

    float *h0, *p0, *p1, *accb, *a2b;
    cudaGetSymbolAddress((void**)&h0,   g_h0);
    cudaGetSymbolAddress((void**)&p0,   g_p0);
    cudaGetSymbolAddress((void**)&p1,   g_p1);
    cudaGetSymbolAddress((void**)&accb, g_accb);
    cudaGetSymbolAddress((void**)&a2b,  g_a2);

    // 1) causal conv as pipelined tf32 mma GEMM: per-batch M=16383, K=512
    mma_gemm_k<0><<<dim3(2, 128, 8), 256>>>(x, 16384LL * 256, 16383, 512, 256,
                                            causal_W, causal_b, h0, 16384LL * 256, 256);

    // 2) first gated layer (tensorized) -> p0 (16382 rows/batch)
    first_gated_mma_k<<<dim3(128, 8), 256>>>(h0, gW0, gb0, fW0, fb0, sW0, sb0, p0);

    // 3) nine dilated gated layers (tensorized; only last residual matters)
    float* bufs[2] = { p0, p1 };
    int cur = 0;
    int Lin = 16382;
    for (int i = 0; i < 9; i++) {
        int d = 2 << i;
        int Lout = Lin - d;
        gated24_mma_k<<<dim3((Lout + 127) / 128, 8), 256>>>(
            bufs[cur], bufs[1 - cur], Lin, Lout, d,
            gate_W + i * 1152, gate_b + i * 24,
            filter_W + i * 1152, filter_b + i * 24,
            scale_W + i * 576, scale_b + i * 24);
        cur ^= 1;
        Lin = Lout;
    }

    // 4) residual combine + res conv (i=8 only) + ReLU -> accb (15360 x 128)
    res_relu_k<<<dim3(120, 8), 256>>>(bufs[1 - cur], bufs[cur],
                                      res_W + 8 * 24 * 128, res_b + 8 * 128, accb);

    // 5) f1: pipelined tf32 GEMM K=128 + ReLU -> a2b (122880 x 256)
    mma_gemm_k<1><<<dim3(2, 960, 1), 256>>>(accb, 0, 122880, 128, 128,
                                            f1_W, f1_b, a2b, 0, 256);

    // 6) f2: pipelined tf32 GEMM K=256 -> logits in d_out
    mma_gemm_k<0><<<dim3(2, 960, 1), 256>>>(a2b, 0, 122880, 256, 256,
                                            f2_W, f2_b, out, 0, 256);

    // 7) softmax over channels, in place
    softmax256_k<<<122880, 256>>>(out);
}

// round 9
// speedup vs baseline: 2.3600x; 1.1386x over previous
#include <cuda_runtime.h>
#include <cstdint>
#include <math.h>

// ---------------- scratch (device globals; no allocation allowed) ----------------
__device__ float g_h0[33554432];          // 8*16384*256  (causal output)
__device__ float g_p0[3145728];           // 8*16384*24   ping
__device__ float g_p1[3145728];           // 8*16384*24   pong
__device__ float g_accb[15728640];        // 8*15360*128  relu(res conv)
__device__ float g_a2[31457280];          // 8*15360*256  relu(f1)

__device__ __forceinline__ uint32_t smem_u32(const void* p) {
    uint32_t a;
    asm("{ .reg .u64 t; cvta.to.shared.u64 t, %1; cvt.u32.u64 %0, t; }" : "=r"(a) : "l"(p));
    return a;
}
__device__ __forceinline__ void cpa16(const void* smem_dst, const void* gsrc) {
    uint32_t a = smem_u32(smem_dst);
    asm volatile("cp.async.cg.shared.global [%0], [%1], 16;" :: "r"(a), "l"(gsrc) : "memory");
}
#define CP_COMMIT() asm volatile("cp.async.commit_group;" ::: "memory")
#define CP_WAIT0()  asm volatile("cp.async.wait_group 0;" ::: "memory")
#define CP_WAIT1()  asm volatile("cp.async.wait_group 1;" ::: "memory")

__device__ __forceinline__ void mma_tf32_16x8x8(float c[4],
                                                const uint32_t a[4], const uint32_t b[2])
{
    asm volatile(
        "mma.sync.aligned.m16n8k8.row.col.f32.tf32.tf32.f32 "
        "{%0,%1,%2,%3}, {%4,%5,%6,%7}, {%8,%9}, {%0,%1,%2,%3};"
        : "+f"(c[0]), "+f"(c[1]), "+f"(c[2]), "+f"(c[3])
        : "r"(a[0]), "r"(a[1]), "r"(a[2]), "r"(a[3]), "r"(b[0]), "r"(b[1]));
}

// combine two (max, sumexp) pairs
__device__ __forceinline__ void sm_comb(float& m, float& s, float m2, float s2) {
    float nm = fmaxf(m, m2);
    s = s * __expf(m - nm) + s2 * __expf(m2 - nm);
    m = nm;
}

// =====================================================================
// tf32 mma.sync GEMM w/ cp.async 2-stage pipeline, BN=256 per CTA.
// C[m,n] = epi( A[m..](K contiguous from row base, stride Arow) x W[K,256] + bias )
// BM=128, BN=256, BK=16, 256 threads (8 warps 2x4), warp tile 64x64.
// EPI: 0 plain, 1 relu, 2 softmax over the 256 cols.
// =====================================================================
template<int EPI>
__global__ void __launch_bounds__(256, 1)
mma_gemm_k(const float* __restrict__ A, long long Abstride,
           int M, int K, int Arow,
           const float* __restrict__ W, const float* __restrict__ bias,
           float* __restrict__ C, long long Cbstride, int Crow)
{
    extern __shared__ float smg[];
    float (*As)[128][20] = reinterpret_cast<float (*)[128][20]>(smg);              // 2*128*20
    float (*Bs)[16][264] = reinterpret_cast<float (*)[16][264]>(smg + 2 * 128 * 20); // 2*16*264

    const int b = blockIdx.z;
    A += (long long)b * Abstride;
    C += (long long)b * Cbstride;
    const int m0 = blockIdx.y * 128;

    const int tid  = threadIdx.x;
    const int wid  = tid >> 5;
    const int lane = tid & 31;
    const int wr = wid & 1;            // m half
    const int wc = wid >> 1;           // n quarter (0..3)
    const int lr = lane >> 2;
    const int lc = lane & 3;

    float acc[4][8][4];
#pragma unroll
    for (int mi = 0; mi < 4; mi++)
#pragma unroll
        for (int ni = 0; ni < 8; ni++)
#pragma unroll
            for (int j = 0; j < 4; j++) acc[mi][ni][j] = 0.f;

    const int arow_ld = tid >> 1;
    const int akq     = (tid & 1) * 8;
    int mg = m0 + arow_ld; if (mg > M - 1) mg = M - 1;
    const float* Ap = A + (long long)mg * Arow;
    const int brow_ld = tid >> 4;          // 0..15
    const int bcol    = (tid & 15) * 16;   // 0..240

    const int nch = K >> 4;

    {
        cpa16(&As[0][arow_ld][akq],     Ap + akq);
        cpa16(&As[0][arow_ld][akq + 4], Ap + akq + 4);
        const float* Wp = W + (long long)brow_ld * 256 + bcol;
        cpa16(&Bs[0][brow_ld][bcol],      Wp);
        cpa16(&Bs[0][brow_ld][bcol + 4],  Wp + 4);
        cpa16(&Bs[0][brow_ld][bcol + 8],  Wp + 8);
        cpa16(&Bs[0][brow_ld][bcol + 12], Wp + 12);
        CP_COMMIT();
    }

#pragma unroll 1
    for (int ic = 0; ic < nch; ic++) {
        const int s = ic & 1;
        if (ic + 1 < nch) {
            const int k1 = (ic + 1) << 4;
            cpa16(&As[s ^ 1][arow_ld][akq],     Ap + k1 + akq);
            cpa16(&As[s ^ 1][arow_ld][akq + 4], Ap + k1 + akq + 4);
            const float* Wp = W + (long long)(k1 + brow_ld) * 256 + bcol;
            cpa16(&Bs[s ^ 1][brow_ld][bcol],      Wp);
            cpa16(&Bs[s ^ 1][brow_ld][bcol + 4],  Wp + 4);
            cpa16(&Bs[s ^ 1][brow_ld][bcol + 8],  Wp + 8);
            cpa16(&Bs[s ^ 1][brow_ld][bcol + 12], Wp + 12);
            CP_COMMIT();
            CP_WAIT1();
        } else {
            CP_WAIT0();
        }
        __syncthreads();

#pragma unroll
        for (int ks = 0; ks < 2; ks++) {
            const int kb = ks * 8;
            uint32_t af[4][4];
#pragma unroll
            for (int mi = 0; mi < 4; mi++) {
                const int mrow = wr * 64 + mi * 16 + lr;
                af[mi][0] = __float_as_uint(As[s][mrow][kb + lc]);
                af[mi][1] = __float_as_uint(As[s][mrow + 8][kb + lc]);
                af[mi][2] = __float_as_uint(As[s][mrow][kb + lc + 4]);
                af[mi][3] = __float_as_uint(As[s][mrow + 8][kb + lc + 4]);
            }
            uint32_t bf[8][2];
#pragma unroll
            for (int ni = 0; ni < 8; ni++) {
                const int ncol = wc * 64 + ni * 8 + lr;
                bf[ni][0] = __float_as_uint(Bs[s][kb + lc][ncol]);
                bf[ni][1] = __float_as_uint(Bs[s][kb + lc + 4][ncol]);
            }
#pragma unroll
            for (int mi = 0; mi < 4; mi++)
#pragma unroll
                for (int ni = 0; ni < 8; ni++)
                    mma_tf32_16x8x8(acc[mi][ni], af[mi], bf[ni]);
        }
        __syncthreads();
    }

    // ---------------- epilogue ----------------
    if (EPI != 2) {
#pragma unroll
        for (int mi = 0; mi < 4; mi++) {
            const int r0 = m0 + wr * 64 + mi * 16 + lr;
            const int r1 = r0 + 8;
#pragma unroll
            for (int ni = 0; ni < 8; ni++) {
                const int col = wc * 64 + ni * 8 + 2 * lc;
                const float b0v = bias[col], b1v = bias[col + 1];
                if (r0 < M) {
                    float2 o;
                    o.x = acc[mi][ni][0] + b0v;
                    o.y = acc[mi][ni][1] + b1v;
                    if (EPI == 1) { o.x = fmaxf(o.x, 0.f); o.y = fmaxf(o.y, 0.f); }
                    *reinterpret_cast<float2*>(C + (long long)r0 * Crow + col) = o;
                }
                if (r1 < M) {
                    float2 o;
                    o.x = acc[mi][ni][2] + b0v;
                    o.y = acc[mi][ni][3] + b1v;
                    if (EPI == 1) { o.x = fmaxf(o.x, 0.f); o.y = fmaxf(o.y, 0.f); }
                    *reinterpret_cast<float2*>(C + (long long)r1 * Crow + col) = o;
                }
            }
        }
    } else {
        // fused softmax over full 256 cols of each row.
        // per thread: 8 rows (mi x {low,high}), 16 cols each.
        float2* red = reinterpret_cast<float2*>(smg);   // [128][4] (mx, sum)
        float mx[8], sme[8];
#pragma unroll
        for (int mi = 0; mi < 4; mi++) {
#pragma unroll
            for (int h = 0; h < 2; h++) {
                float m = -1e30f;
#pragma unroll
                for (int ni = 0; ni < 8; ni++) {
                    const int col = wc * 64 + ni * 8 + 2 * lc;
                    m = fmaxf(m, fmaxf(acc[mi][ni][2 * h] + bias[col],
                                       acc[mi][ni][2 * h + 1] + bias[col + 1]));
                }
                float ss = 0.f;
#pragma unroll
                for (int ni = 0; ni < 8; ni++) {
                    const int col = wc * 64 + ni * 8 + 2 * lc;
                    ss += __expf(acc[mi][ni][2 * h] + bias[col] - m);
                    ss += __expf(acc[mi][ni][2 * h + 1] + bias[col + 1] - m);
                }
                mx[mi * 2 + h] = m; sme[mi * 2 + h] = ss;
            }
        }
        // reduce over lc-group (lanes xor 1, 2 share the same row)
#pragma unroll
        for (int o = 1; o <= 2; o <<= 1) {
#pragma unroll
            for (int q = 0; q < 8; q++) {
                float m2 = __shfl_xor_sync(0xffffffffu, mx[q], o);
                float s2 = __shfl_xor_sync(0xffffffffu, sme[q], o);
                sm_comb(mx[q], sme[q], m2, s2);
            }
        }
        if (lc == 0) {
#pragma unroll
            for (int mi = 0; mi < 4; mi++) {
#pragma unroll
                for (int h = 0; h < 2; h++) {
                    const int rloc = wr * 64 + mi * 16 + h * 8 + lr;
                    red[rloc * 4 + wc] = make_float2(mx[mi * 2 + h], sme[mi * 2 + h]);
                }
            }
        }
        __syncthreads();
#pragma unroll
        for (int mi = 0; mi < 4; mi++) {
#pragma unroll
            for (int h = 0; h < 2; h++) {
                const int rloc = wr * 64 + mi * 16 + h * 8 + lr;
                float2 p0 = red[rloc * 4 + 0];
                float gm = p0.x, gs = p0.y;
#pragma unroll
                for (int q = 1; q < 4; q++) {
                    float2 pq = red[rloc * 4 + q];
                    sm_comb(gm, gs, pq.x, pq.y);
                }
                const float inv = 1.f / gs;
                const int r = m0 + rloc;
                if (r < M) {
#pragma unroll
                    for (int ni = 0; ni < 8; ni++) {
                        const int col = wc * 64 + ni * 8 + 2 * lc;
                        float2 o;
                        o.x = __expf(acc[mi][ni][2 * h] + bias[col] - gm) * inv;
                        o.y = __expf(acc[mi][ni][2 * h + 1] + bias[col + 1] - gm) * inv;
                        *reinterpret_cast<float2*>(C + (long long)r * Crow + col) = o;
                    }
                }
            }
        }
    }
}

// =====================================================================
// Dilated gated 24-ch layer, 256 rows/CTA, tensorized, single block sync.
// Stage1: A[256x48] x Wc[48x48] -> act -> P[256x24]
// Stage2: P x sW[24x24] (+sb) -> out   (or, LAST:)
// Stage2L: q = stage2 + sb + trimmed;  Stage3: q x res_W[24x128] + rb, relu -> accb
// =====================================================================
template<int LAST>
__global__ void __launch_bounds__(256)
gated24b_k(const float* __restrict__ in, float* __restrict__ out,
           int Lout, int d,
           const float* __restrict__ gW, const float* __restrict__ gb,
           const float* __restrict__ fW, const float* __restrict__ fb,
           const float* __restrict__ sW, const float* __restrict__ sb,
           const float* __restrict__ Rg, const float* __restrict__ rb,
           float* __restrict__ outa)
{
    extern __shared__ float smf[];
    float* As = smf;                     // [256][52]
    float* Wc = As + 256 * 52;           // [48][56]
    float* W2 = Wc + 48 * 56;            // [24][40]
    float* T  = W2 + 24 * 40;            // [256][28]  (LAST only)
    float* Rw = T + 256 * 28;            // [24][136]  (LAST only)
    float* P  = As;                      // [256][28] alias (warp-private rows after sync)

    const int b  = blockIdx.y;
    const int m0 = blockIdx.x * 256;
    const float* Ab = in + (long long)b * 16384 * 24;

    const int tid = threadIdx.x;
    const int wid = tid >> 5;
    const int lane = tid & 31;
    const int lr = lane >> 2;
    const int lc = lane & 3;
    const int mrow = wid * 32;

    for (int i = tid; i < 2304; i += 256) {
        int k = i / 48, n = i % 48;
        Wc[k * 56 + n] = (n < 24) ? gW[k * 24 + n] : fW[k * 24 + (n - 24)];
    }
    for (int i = tid; i < 576; i += 256) W2[(i / 24) * 40 + (i % 24)] = sW[i];
    if (LAST) {
        for (int i = tid; i < 768; i += 256) {
            int k = i >> 5, c = (i & 31) * 4;
            *reinterpret_cast<float4*>(&Rw[k * 136 + c]) =
                *reinterpret_cast<const float4*>(Rg + i * 4);
        }
    }

    // A fill: 256 rows x (24 + 24); 6 float4 per row per source
    for (int v = tid; v < 1536; v += 256) {
        int t = v / 6, q = (v % 6) * 4;
        int r0 = m0 + t;                        // <= 16383 always
        *reinterpret_cast<float4*>(&As[t * 52 + q]) =
            *reinterpret_cast<const float4*>(Ab + (long long)r0 * 24 + q);
        int r1 = m0 + t + d; if (r1 > 16383) r1 = 16383;
        *reinterpret_cast<float4*>(&As[t * 52 + 24 + q]) =
            *reinterpret_cast<const float4*>(Ab + (long long)r1 * 24 + q);
        if (LAST) {
            *reinterpret_cast<float4*>(&T[t * 28 + q]) =
                *reinterpret_cast<const float4*>(Ab + (long long)(m0 + t + 256) * 24 + q);
        }
    }
    __syncthreads();

    // ---- stage 1 ----
    float acc[2][6][4];
#pragma unroll
    for (int mi = 0; mi < 2; mi++)
#pragma unroll
        for (int ni = 0; ni < 6; ni++)
#pragma unroll
            for (int j = 0; j < 4; j++) acc[mi][ni][j] = 0.f;

#pragma unroll
    for (int ks = 0; ks < 6; ks++) {
        const int kb = ks * 8;
        uint32_t a[2][4];
#pragma unroll
        for (int mi = 0; mi < 2; mi++) {
            const int r = mrow + mi * 16 + lr;
            a[mi][0] = __float_as_uint(As[r * 52 + kb + lc]);
            a[mi][1] = __float_as_uint(As[(r + 8) * 52 + kb + lc]);
            a[mi][2] = __float_as_uint(As[r * 52 + kb + lc + 4]);
            a[mi][3] = __float_as_uint(As[(r + 8) * 52 + kb + lc + 4]);
        }
#pragma unroll
        for (int ni = 0; ni < 6; ni++) {
            uint32_t bf[2];
            bf[0] = __float_as_uint(Wc[(kb + lc) * 56 + ni * 8 + lr]);
            bf[1] = __float_as_uint(Wc[(kb + lc + 4) * 56 + ni * 8 + lr]);
            mma_tf32_16x8x8(acc[0][ni], a[0], bf);
            mma_tf32_16x8x8(acc[1][ni], a[1], bf);
        }
    }
    __syncthreads();   // all As reads complete before P alias writes (cross-warp overlap)

    // ---- activation -> P (warp-private rows) ----
#pragma unroll
    for (int mi = 0; mi < 2; mi++)
#pragma unroll
        for (int ni = 0; ni < 3; ni++)
#pragma unroll
            for (int j = 0; j < 4; j++) {
                const int c = ni * 8 + 2 * lc + (j & 1);
                const int m = mrow + mi * 16 + lr + ((j >> 1) << 3);
                float g = acc[mi][ni][j]     + gb[c];
                float f = acc[mi][ni + 3][j] + fb[c];
                P[m * 28 + c] = tanhf(f) * (1.f / (1.f + __expf(-g)));
            }
    __syncwarp();

    // ---- stage 2 ----
    float acc2[2][3][4];
#pragma unroll
    for (int mi = 0; mi < 2; mi++)
#pragma unroll
        for (int ni = 0; ni < 3; ni++)
#pragma unroll
            for (int j = 0; j < 4; j++) acc2[mi][ni][j] = 0.f;

#pragma unroll
    for (int ks = 0; ks < 3; ks++) {
        const int kb = ks * 8;
        uint32_t a[2][4];
#pragma unroll
        for (int mi = 0; mi < 2; mi++) {
            const int r = mrow + mi * 16 + lr;
            a[mi][0] = __float_as_uint(P[r * 28 + kb + lc]);
            a[mi][1] = __float_as_uint(P[(r + 8) * 28 + kb + lc]);
            a[mi][2] = __float_as_uint(P[r * 28 + kb + lc + 4]);
            a[mi][3] = __float_as_uint(P[(r + 8) * 28 + kb + lc + 4]);
        }
#pragma unroll
        for (int ni = 0; ni < 3; ni++) {
            uint32_t bf[2];
            bf[0] = __float_as_uint(W2[(kb + lc) * 40 + ni * 8 + lr]);
            bf[1] = __float_as_uint(W2[(kb + lc + 4) * 40 + ni * 8 + lr]);
            mma_tf32_16x8x8(acc2[0][ni], a[0], bf);
            mma_tf32_16x8x8(acc2[1][ni], a[1], bf);
        }
    }

    if (!LAST) {
        float* O = out + (long long)b * 16384 * 24;
#pragma unroll
        for (int mi = 0; mi < 2; mi++) {
            const int r0 = m0 + mrow + mi * 16 + lr;
            const int r1 = r0 + 8;
#pragma unroll
            for (int ni = 0; ni < 3; ni++) {
                const int col = ni * 8 + 2 * lc;
                if (r0 < Lout) {
                    float2 o = { acc2[mi][ni][0] + sb[col], acc2[mi][ni][1] + sb[col + 1] };
                    *reinterpret_cast<float2*>(O + (long long)r0 * 24 + col) = o;
                }
                if (r1 < Lout) {
                    float2 o = { acc2[mi][ni][2] + sb[col], acc2[mi][ni][3] + sb[col + 1] };
                    *reinterpret_cast<float2*>(O + (long long)r1 * 24 + col) = o;
                }
            }
        }
    } else {
        // q = stage2 + sb + trimmed -> back into P (warp-private, reads done)
#pragma unroll
        for (int mi = 0; mi < 2; mi++)
#pragma unroll
            for (int ni = 0; ni < 3; ni++)
#pragma unroll
                for (int j = 0; j < 4; j++) {
                    const int c = ni * 8 + 2 * lc + (j & 1);
                    const int m = mrow + mi * 16 + lr + ((j >> 1) << 3);
                    P[m * 28 + c] = acc2[mi][ni][j] + sb[c] + T[m * 28 + c];
                }
        __syncwarp();

        // stage 3: q[256x24] x R[24x128] + rb, relu -> accb, two 64-col halves
        float* O = outa + (long long)b * 15360 * 128 + (long long)m0 * 128;
#pragma unroll
        for (int h = 0; h < 2; h++) {
            float acc3[2][8][4];
#pragma unroll
            for (int mi = 0; mi < 2; mi++)
#pragma unroll
                for (int ni = 0; ni < 8; ni++)
#pragma unroll
                    for (int j = 0; j < 4; j++) acc3[mi][ni][j] = 0.f;

#pragma unroll
            for (int ks = 0; ks < 3; ks++) {
                const int kb = ks * 8;
                uint32_t a[2][4];
#pragma unroll
                for (int mi = 0; mi < 2; mi++) {
                    const int r = mrow + mi * 16 + lr;
                    a[mi][0] = __float_as_uint(P[r * 28 + kb + lc]);
                    a[mi][1] = __float_as_uint(P[(r + 8) * 28 + kb + lc]);
                    a[mi][2] = __float_as_uint(P[r * 28 + kb + lc + 4]);
                    a[mi][3] = __float_as_uint(P[(r + 8) * 28 + kb + lc + 4]);
                }
#pragma unroll
                for (int ni = 0; ni < 8; ni++) {
                    uint32_t bf[2];
                    bf[0] = __float_as_uint(Rw[(kb + lc) * 136 + h * 64 + ni * 8 + lr]);
                    bf[1] = __float_as_uint(Rw[(kb + lc + 4) * 136 + h * 64 + ni * 8 + lr]);
                    mma_tf32_16x8x8(acc3[0][ni], a[0], bf);
                    mma_tf32_16x8x8(acc3[1][ni], a[1], bf);
                }
            }
#pragma unroll
            for (int mi = 0; mi < 2; mi++) {
                const int r0 = mrow + mi * 16 + lr;
                const int r1 = r0 + 8;
#pragma unroll
                for (int ni = 0; ni < 8; ni++) {
                    const int col = h * 64 + ni * 8 + 2 * lc;
                    float2 o0 = { fmaxf(acc3[mi][ni][0] + rb[col], 0.f),
                                  fmaxf(acc3[mi][ni][1] + rb[col + 1], 0.f) };
                    *reinterpret_cast<float2*>(O + (long long)r0 * 128 + col) = o0;
                    float2 o1 = { fmaxf(acc3[mi][ni][2] + rb[col], 0.f),
                                  fmaxf(acc3[mi][ni][3] + rb[col + 1], 0.f) };
                    *reinterpret_cast<float2*>(O + (long long)r1 * 128 + col) = o1;
                }
            }
        }
    }
}

// =====================================================================
// First gated layer, tensorized + cp.async pipelined over K=512.
// =====================================================================
__global__ void __launch_bounds__(256)
first_gated_mma_k(const float* __restrict__ h0,
                  const float* __restrict__ gW, const float* __restrict__ gb,
                  const float* __restrict__ fW, const float* __restrict__ fb,
                  const float* __restrict__ sW, const float* __restrict__ sb,
                  float* __restrict__ out)
{
    __shared__ __align__(16) float As[2][128][20];
    __shared__ float Bs[2][16][56];
    __shared__ float W2[24][56];
    float* P = &As[0][0][0];       // [128][28] alias after mainloop

    const int M  = 16382;
    const int b  = blockIdx.y;
    const int m0 = blockIdx.x * 128;
    const float* A = h0 + (long long)b * 16384 * 256;

    const int tid = threadIdx.x;
    const int wid = tid >> 5;
    const int lane = tid & 31;
    const int lr = lane >> 2;
    const int lc = lane & 3;
    const int mrow = wid * 16;

    const int arow_ld = tid >> 1;
    const int akq     = (tid & 1) * 8;
    int mg = m0 + arow_ld; if (mg > M - 1) mg = M - 1;
    const float* Ap = A + (long long)mg * 256;

    for (int i = tid; i < 576; i += 256) W2[i / 24][i % 24] = sW[i];

    for (int i = tid; i < 768; i += 256) {
        int kk = i / 48, n = i % 48;
        Bs[0][kk][n] = (n < 24) ? gW[kk * 24 + n] : fW[kk * 24 + (n - 24)];
    }
    cpa16(&As[0][arow_ld][akq],     Ap + akq);
    cpa16(&As[0][arow_ld][akq + 4], Ap + akq + 4);
    CP_COMMIT();

    float acc[6][4];
#pragma unroll
    for (int ni = 0; ni < 6; ni++)
#pragma unroll
        for (int j = 0; j < 4; j++) acc[ni][j] = 0.f;

#pragma unroll 1
    for (int ic = 0; ic < 32; ic++) {
        const int s = ic & 1;
        if (ic < 31) {
            const int k1 = (ic + 1) * 16;
            for (int i = tid; i < 768; i += 256) {
                int kk = i / 48, n = i % 48;
                Bs[s ^ 1][kk][n] = (n < 24) ? gW[(k1 + kk) * 24 + n]
                                            : fW[(k1 + kk) * 24 + (n - 24)];
            }
            cpa16(&As[s ^ 1][arow_ld][akq],     Ap + k1 + akq);
            cpa16(&As[s ^ 1][arow_ld][akq + 4], Ap + k1 + akq + 4);
            CP_COMMIT();
            CP_WAIT1();
        } else {
            CP_WAIT0();
        }
        __syncthreads();

#pragma unroll
        for (int ks = 0; ks < 2; ks++) {
            const int kb = ks * 8;
            uint32_t a[4];
            a[0] = __float_as_uint(As[s][mrow + lr][kb + lc]);
            a[1] = __float_as_uint(As[s][mrow + lr + 8][kb + lc]);
            a[2] = __float_as_uint(As[s][mrow + lr][kb + lc + 4]);
            a[3] = __float_as_uint(As[s][mrow + lr + 8][kb + lc + 4]);
#pragma unroll
            for (int ni = 0; ni < 6; ni++) {
                uint32_t bf[2];
                bf[0] = __float_as_uint(Bs[s][kb + lc][ni * 8 + lr]);
                bf[1] = __float_as_uint(Bs[s][kb + lc + 4][ni * 8 + lr]);
                mma_tf32_16x8x8(acc[ni], a, bf);
            }
        }
        __syncthreads();
    }

#pragma unroll
    for (int ni = 0; ni < 3; ni++) {
        const int col = ni * 8 + 2 * lc;
#pragma unroll
        for (int j = 0; j < 4; j++) {
            const int c = col + (j & 1);
            float g = acc[ni][j]     + gb[c];
            float f = acc[ni + 3][j] + fb[c];
            float p = tanhf(f) * (1.f / (1.f + __expf(-g)));
            const int m = mrow + lr + ((j >> 1) << 3);
            P[m * 28 + c] = p;
        }
    }
    __syncthreads();

    float acc2[3][4];
#pragma unroll
    for (int ni = 0; ni < 3; ni++)
#pragma unroll
        for (int j = 0; j < 4; j++) acc2[ni][j] = 0.f;

#pragma unroll
    for (int ks = 0; ks < 3; ks++) {
        const int kb = ks * 8;
        uint32_t a[4];
        a[0] = __float_as_uint(P[(mrow + lr) * 28 + kb + lc]);
        a[1] = __float_as_uint(P[(mrow + lr + 8) * 28 + kb + lc]);
        a[2] = __float_as_uint(P[(mrow + lr) * 28 + kb + lc + 4]);
        a[3] = __float_as_uint(P[(mrow + lr + 8) * 28 + kb + lc + 4]);
#pragma unroll
        for (int ni = 0; ni < 3; ni++) {
            uint32_t bf[2];
            bf[0] = __float_as_uint(W2[kb + lc][ni * 8 + lr]);
            bf[1] = __float_as_uint(W2[kb + lc + 4][ni * 8 + lr]);
            mma_tf32_16x8x8(acc2[ni], a, bf);
        }
    }

    float* O = out + (long long)b * 16384 * 24;
    const int r0 = m0 + mrow + lr;
    const int r1 = r0 + 8;
#pragma unroll
    for (int ni = 0; ni < 3; ni++) {
        const int col = ni * 8 + 2 * lc;
        if (r0 < M) {
            float2 o = { acc2[ni][0] + sb[col], acc2[ni][1] + sb[col + 1] };
            *reinterpret_cast<float2*>(O + (long long)r0 * 24 + col) = o;
        }
        if (r1 < M) {
            float2 o = { acc2[ni][2] + sb[col], acc2[ni][3] + sb[col + 1] };
            *reinterpret_cast<float2*>(O + (long long)r1 * 24 + col) = o;
        }
    }
}

// =====================================================================
extern "C" void kernel_launch(void* const* d_in, const int* in_sizes, int n_in,
                              void* d_out, int out_size)
{
    const float* x        = (const float*)d_in[0];
    const float* causal_W = (const float*)d_in[1];
    const float* causal_b = (const float*)d_in[2];
    const float* gW0      = (const float*)d_in[3];
    const float* gb0      = (const float*)d_in[4];
    const float* fW0      = (const float*)d_in[5];
    const float* fb0      = (const float*)d_in[6];
    const float* sW0      = (const float*)d_in[7];
    const float* sb0      = (const float*)d_in[8];
    const float* gate_W   = (const float*)d_in[9];
    const float* gate_b   = (const float*)d_in[10];
    const float* filter_W = (const float*)d_in[11];
    const float* filter_b = (const float*)d_in[12];
    const float* scale_W  = (const float*)d_in[13];
    const float* scale_b  = (const float*)d_in[14];
    const float* res_W    = (const float*)d_in[15];
    const float* res_b    = (const float*)d_in[16];
    const float* f1_W     = (const float*)d_in[17];
    const float* f1_b     = (const float*)d_in[18];
    const float* f2_W     = (const float*)d_in[19];
    const float* f2_b     = (const float*)d_in[20];
    float* out = (float*)d_out;

    float *h0, *p0, *p1, *accb, *a2b;
    cudaGetSymbolAddress((void**)&h0,   g_h0);
    cudaGetSymbolAddress((void**)&p0,   g_p0);
    cudaGetSymbolAddress((void**)&p1,   g_p1);
    cudaGetSymbolAddress((void**)&accb, g_accb);
    cudaGetSymbolAddress((void**)&a2b,  g_a2);

    const int GEMM_SMEM  = (2 * 128 * 20 + 2 * 16 * 264) * 4;                     // 54272
    const int G24_SMEM   = (256 * 52 + 48 * 56 + 24 * 40) * 4;                    // 67840
    const int G24L_SMEM  = G24_SMEM + (256 * 28 + 24 * 136) * 4;                  // 109568
    cudaFuncSetAttribute(mma_gemm_k<0>, cudaFuncAttributeMaxDynamicSharedMemorySize, GEMM_SMEM);
    cudaFuncSetAttribute(mma_gemm_k<1>, cudaFuncAttributeMaxDynamicSharedMemorySize, GEMM_SMEM);
    cudaFuncSetAttribute(mma_gemm_k<2>, cudaFuncAttributeMaxDynamicSharedMemorySize, GEMM_SMEM);
    cudaFuncSetAttribute(gated24b_k<0>, cudaFuncAttributeMaxDynamicSharedMemorySize, G24_SMEM);
    cudaFuncSetAttribute(gated24b_k<1>, cudaFuncAttributeMaxDynamicSharedMemorySize, G24L_SMEM);

    // 1) causal conv as pipelined tf32 mma GEMM: per-batch M=16383, K=512
    mma_gemm_k<0><<<dim3(1, 128, 8), 256, GEMM_SMEM>>>(
        x, 16384LL * 256, 16383, 512, 256, causal_W, causal_b, h0, 16384LL * 256, 256);

    // 2) first gated layer (tensorized) -> p0 (16382 rows/batch)
    first_gated_mma_k<<<dim3(128, 8), 256>>>(h0, gW0, gb0, fW0, fb0, sW0, sb0, p0);

    // 3) eight dilated gated layers -> ping-pong; ninth fused with res+relu
    float* bufs[2] = { p0, p1 };
    int cur = 0;
    int Lin = 16382;
    for (int i = 0; i < 8; i++) {
        int d = 2 << i;
        int Lout = Lin - d;
        gated24b_k<0><<<dim3((Lout + 255) / 256, 8), 256, G24_SMEM>>>(
            bufs[cur], bufs[1 - cur], Lout, d,
            gate_W + i * 1152, gate_b + i * 24,
            filter_W + i * 1152, filter_b + i * 24,
            scale_W + i * 576, scale_b + i * 24,
            nullptr, nullptr, nullptr);
        cur ^= 1;
        Lin = Lout;
    }
    // layer 9 (i=8, d=512): fused gated + residual + res conv + relu -> accb
    gated24b_k<1><<<dim3(60, 8), 256, G24L_SMEM>>>(
        bufs[cur], nullptr, 15360, 512,
        gate_W + 8 * 1152, gate_b + 8 * 24,
        filter_W + 8 * 1152, filter_b + 8 * 24,
        scale_W + 8 * 576, scale_b + 8 * 24,
        res_W + 8 * 3072, res_b + 8 * 128, accb);

    // 4) f1: pipelined tf32 GEMM K=128 + ReLU -> a2b (122880 x 256)
    mma_gemm_k<1><<<dim3(1, 960, 1), 256, GEMM_SMEM>>>(
        accb, 0, 122880, 128, 128, f1_W, f1_b, a2b, 0, 256);

    // 5) f2: pipelined tf32 GEMM K=256 + fused softmax -> d_out
    mma_gemm_k<2><<<dim3(1, 960, 1), 256, GEMM_SMEM>>>(
        a2b, 0, 122880, 256, 256, f2_W, f2_b, out, 0, 256);
}

// round 14
// speedup vs baseline: 2.4987x; 1.0588x over previous
#include <cuda_runtime.h>
#include <cstdint>
#include <math.h>

// ---------------- scratch (device globals; no allocation allowed) ----------------
__device__ float g_h0[33554432];          // 8*16384*256  (causal output)
__device__ float g_p0[3145728];           // 8*16384*24   ping
__device__ float g_p1[3145728];           // 8*16384*24   pong
__device__ float g_accb[15728640];        // 8*15360*128  relu(res conv)
__device__ float g_a2[31457280];          // 8*15360*256  relu(f1)

__device__ __forceinline__ uint32_t smem_u32(const void* p) {
    uint32_t a;
    asm("{ .reg .u64 t; cvta.to.shared.u64 t, %1; cvt.u32.u64 %0, t; }" : "=r"(a) : "l"(p));
    return a;
}
__device__ __forceinline__ void cpa16(const void* smem_dst, const void* gsrc) {
    uint32_t a = smem_u32(smem_dst);
    asm volatile("cp.async.cg.shared.global [%0], [%1], 16;" :: "r"(a), "l"(gsrc) : "memory");
}
#define CP_COMMIT() asm volatile("cp.async.commit_group;" ::: "memory")
#define CP_WAIT0()  asm volatile("cp.async.wait_group 0;" ::: "memory")
#define CP_WAIT1()  asm volatile("cp.async.wait_group 1;" ::: "memory")

__device__ __forceinline__ void mma_tf32_16x8x8(float c[4],
                                                const uint32_t a[4], const uint32_t b[2])
{
    asm volatile(
        "mma.sync.aligned.m16n8k8.row.col.f32.tf32.tf32.f32 "
        "{%0,%1,%2,%3}, {%4,%5,%6,%7}, {%8,%9}, {%0,%1,%2,%3};"
        : "+f"(c[0]), "+f"(c[1]), "+f"(c[2]), "+f"(c[3])
        : "r"(a[0]), "r"(a[1]), "r"(a[2]), "r"(a[3]), "r"(b[0]), "r"(b[1]));
}

// combine two (max, sumexp) pairs
__device__ __forceinline__ void sm_comb(float& m, float& s, float m2, float s2) {
    float nm = fmaxf(m, m2);
    s = s * __expf(m - nm) + s2 * __expf(m2 - nm);
    m = nm;
}

// =====================================================================
// tf32 mma.sync GEMM w/ cp.async 2-stage pipeline, BN=256 per CTA.
// EPI: 0 plain, 1 relu, 2 softmax over the 256 cols.
// =====================================================================
template<int EPI>
__global__ void __launch_bounds__(256, 1)
mma_gemm_k(const float* __restrict__ A, long long Abstride,
           int M, int K, int Arow,
           const float* __restrict__ W, const float* __restrict__ bias,
           float* __restrict__ C, long long Cbstride, int Crow)
{
    extern __shared__ float smg[];
    float (*As)[128][20] = reinterpret_cast<float (*)[128][20]>(smg);
    float (*Bs)[16][264] = reinterpret_cast<float (*)[16][264]>(smg + 2 * 128 * 20);

    const int b = blockIdx.z;
    A += (long long)b * Abstride;
    C += (long long)b * Cbstride;
    const int m0 = blockIdx.y * 128;

    const int tid  = threadIdx.x;
    const int wid  = tid >> 5;
    const int lane = tid & 31;
    const int wr = wid & 1;
    const int wc = wid >> 1;
    const int lr = lane >> 2;
    const int lc = lane & 3;

    float acc[4][8][4];
#pragma unroll
    for (int mi = 0; mi < 4; mi++)
#pragma unroll
        for (int ni = 0; ni < 8; ni++)
#pragma unroll
            for (int j = 0; j < 4; j++) acc[mi][ni][j] = 0.f;

    const int arow_ld = tid >> 1;
    const int akq     = (tid & 1) * 8;
    int mg = m0 + arow_ld; if (mg > M - 1) mg = M - 1;
    const float* Ap = A + (long long)mg * Arow;
    const int brow_ld = tid >> 4;
    const int bcol    = (tid & 15) * 16;

    const int nch = K >> 4;

    {
        cpa16(&As[0][arow_ld][akq],     Ap + akq);
        cpa16(&As[0][arow_ld][akq + 4], Ap + akq + 4);
        const float* Wp = W + (long long)brow_ld * 256 + bcol;
        cpa16(&Bs[0][brow_ld][bcol],      Wp);
        cpa16(&Bs[0][brow_ld][bcol + 4],  Wp + 4);
        cpa16(&Bs[0][brow_ld][bcol + 8],  Wp + 8);
        cpa16(&Bs[0][brow_ld][bcol + 12], Wp + 12);
        CP_COMMIT();
    }

#pragma unroll 1
    for (int ic = 0; ic < nch; ic++) {
        const int s = ic & 1;
        if (ic + 1 < nch) {
            const int k1 = (ic + 1) << 4;
            cpa16(&As[s ^ 1][arow_ld][akq],     Ap + k1 + akq);
            cpa16(&As[s ^ 1][arow_ld][akq + 4], Ap + k1 + akq + 4);
            const float* Wp = W + (long long)(k1 + brow_ld) * 256 + bcol;
            cpa16(&Bs[s ^ 1][brow_ld][bcol],      Wp);
            cpa16(&Bs[s ^ 1][brow_ld][bcol + 4],  Wp + 4);
            cpa16(&Bs[s ^ 1][brow_ld][bcol + 8],  Wp + 8);
            cpa16(&Bs[s ^ 1][brow_ld][bcol + 12], Wp + 12);
            CP_COMMIT();
            CP_WAIT1();
        } else {
            CP_WAIT0();
        }
        __syncthreads();

#pragma unroll
        for (int ks = 0; ks < 2; ks++) {
            const int kb = ks * 8;
            uint32_t af[4][4];
#pragma unroll
            for (int mi = 0; mi < 4; mi++) {
                const int mrow = wr * 64 + mi * 16 + lr;
                af[mi][0] = __float_as_uint(As[s][mrow][kb + lc]);
                af[mi][1] = __float_as_uint(As[s][mrow + 8][kb + lc]);
                af[mi][2] = __float_as_uint(As[s][mrow][kb + lc + 4]);
                af[mi][3] = __float_as_uint(As[s][mrow + 8][kb + lc + 4]);
            }
            uint32_t bf[8][2];
#pragma unroll
            for (int ni = 0; ni < 8; ni++) {
                const int ncol = wc * 64 + ni * 8 + lr;
                bf[ni][0] = __float_as_uint(Bs[s][kb + lc][ncol]);
                bf[ni][1] = __float_as_uint(Bs[s][kb + lc + 4][ncol]);
            }
#pragma unroll
            for (int mi = 0; mi < 4; mi++)
#pragma unroll
                for (int ni = 0; ni < 8; ni++)
                    mma_tf32_16x8x8(acc[mi][ni], af[mi], bf[ni]);
        }
        __syncthreads();
    }

    if (EPI != 2) {
#pragma unroll
        for (int mi = 0; mi < 4; mi++) {
            const int r0 = m0 + wr * 64 + mi * 16 + lr;
            const int r1 = r0 + 8;
#pragma unroll
            for (int ni = 0; ni < 8; ni++) {
                const int col = wc * 64 + ni * 8 + 2 * lc;
                const float b0v = bias[col], b1v = bias[col + 1];
                if (r0 < M) {
                    float2 o;
                    o.x = acc[mi][ni][0] + b0v;
                    o.y = acc[mi][ni][1] + b1v;
                    if (EPI == 1) { o.x = fmaxf(o.x, 0.f); o.y = fmaxf(o.y, 0.f); }
                    *reinterpret_cast<float2*>(C + (long long)r0 * Crow + col) = o;
                }
                if (r1 < M) {
                    float2 o;
                    o.x = acc[mi][ni][2] + b0v;
                    o.y = acc[mi][ni][3] + b1v;
                    if (EPI == 1) { o.x = fmaxf(o.x, 0.f); o.y = fmaxf(o.y, 0.f); }
                    *reinterpret_cast<float2*>(C + (long long)r1 * Crow + col) = o;
                }
            }
        }
    } else {
        float2* red = reinterpret_cast<float2*>(smg);   // [128][4]
        float mx[8], sme[8];
#pragma unroll
        for (int mi = 0; mi < 4; mi++) {
#pragma unroll
            for (int h = 0; h < 2; h++) {
                float m = -1e30f;
#pragma unroll
                for (int ni = 0; ni < 8; ni++) {
                    const int col = wc * 64 + ni * 8 + 2 * lc;
                    m = fmaxf(m, fmaxf(acc[mi][ni][2 * h] + bias[col],
                                       acc[mi][ni][2 * h + 1] + bias[col + 1]));
                }
                float ss = 0.f;
#pragma unroll
                for (int ni = 0; ni < 8; ni++) {
                    const int col = wc * 64 + ni * 8 + 2 * lc;
                    ss += __expf(acc[mi][ni][2 * h] + bias[col] - m);
                    ss += __expf(acc[mi][ni][2 * h + 1] + bias[col + 1] - m);
                }
                mx[mi * 2 + h] = m; sme[mi * 2 + h] = ss;
            }
        }
#pragma unroll
        for (int o = 1; o <= 2; o <<= 1) {
#pragma unroll
            for (int q = 0; q < 8; q++) {
                float m2 = __shfl_xor_sync(0xffffffffu, mx[q], o);
                float s2 = __shfl_xor_sync(0xffffffffu, sme[q], o);
                sm_comb(mx[q], sme[q], m2, s2);
            }
        }
        if (lc == 0) {
#pragma unroll
            for (int mi = 0; mi < 4; mi++)
#pragma unroll
                for (int h = 0; h < 2; h++) {
                    const int rloc = wr * 64 + mi * 16 + h * 8 + lr;
                    red[rloc * 4 + wc] = make_float2(mx[mi * 2 + h], sme[mi * 2 + h]);
                }
        }
        __syncthreads();
#pragma unroll
        for (int mi = 0; mi < 4; mi++) {
#pragma unroll
            for (int h = 0; h < 2; h++) {
                const int rloc = wr * 64 + mi * 16 + h * 8 + lr;
                float2 p0 = red[rloc * 4 + 0];
                float gm = p0.x, gs = p0.y;
#pragma unroll
                for (int q = 1; q < 4; q++) {
                    float2 pq = red[rloc * 4 + q];
                    sm_comb(gm, gs, pq.x, pq.y);
                }
                const float inv = 1.f / gs;
                const int r = m0 + rloc;
                if (r < M) {
#pragma unroll
                    for (int ni = 0; ni < 8; ni++) {
                        const int col = wc * 64 + ni * 8 + 2 * lc;
                        float2 o;
                        o.x = __expf(acc[mi][ni][2 * h] + bias[col] - gm) * inv;
                        o.y = __expf(acc[mi][ni][2 * h + 1] + bias[col + 1] - gm) * inv;
                        *reinterpret_cast<float2*>(C + (long long)r * Crow + col) = o;
                    }
                }
            }
        }
    }
}

// =====================================================================
// PAIR-FUSED dilated gated layers (dilations D1, then D2).
// Per CTA: 256 output rows of layer-2; stage1 computes 256+D2 mid rows.
// A stored as plain input rows [ASR][28]; fragments pick row r (k<24)
// or r+D (k>=24) — no gather copies. Two __syncthreads total.
// =====================================================================
template<int D1, int D2>
__global__ void __launch_bounds__(256)
gated24_pair_k(const float* __restrict__ in, float* __restrict__ out, int Lout,
               const float* __restrict__ gW1, const float* __restrict__ gb1,
               const float* __restrict__ fW1, const float* __restrict__ fb1,
               const float* __restrict__ sW1, const float* __restrict__ sb1,
               const float* __restrict__ gW2, const float* __restrict__ gb2,
               const float* __restrict__ fW2, const float* __restrict__ fb2,
               const float* __restrict__ sW2, const float* __restrict__ sb2)
{
    constexpr int MM  = 256 + D2;                   // mid rows needed
    constexpr int RW  = ((MM + 127) / 128) * 16;    // stage1 rows per warp
    constexpr int R8  = RW * 8;                     // stage1 computed rows
    constexpr int MI  = RW / 16;                    // stage1 m16 tiles per warp
    constexpr int ASR = R8 + D1;                    // input rows loaded

    extern __shared__ float smf[];
    float* As  = smf;                   // [ASR][28]
    float* P   = As + ASR * 28;         // [R8][28]
    float* Wc1 = P + R8 * 28;           // [48][56]
    float* W21 = Wc1 + 48 * 56;         // [24][40]
    float* Wc2 = W21 + 24 * 40;         // [48][56]
    float* W22 = Wc2 + 48 * 56;         // [24][40]

    const int b  = blockIdx.y;
    const int m0 = blockIdx.x * 256;
    const float* Ab = in + (long long)b * 16384 * 24;

    const int tid = threadIdx.x;
    const int wid = tid >> 5;
    const int lane = tid & 31;
    const int lr = lane >> 2;
    const int lc = lane & 3;

    // ---- fills ----
    for (int i = tid; i < 2304; i += 256) {
        int k = i / 48, n = i % 48;
        Wc1[k * 56 + n] = (n < 24) ? gW1[k * 24 + n] : fW1[k * 24 + (n - 24)];
        Wc2[k * 56 + n] = (n < 24) ? gW2[k * 24 + n] : fW2[k * 24 + (n - 24)];
    }
    for (int i = tid; i < 576; i += 256) {
        W21[(i / 24) * 40 + (i % 24)] = sW1[i];
        W22[(i / 24) * 40 + (i % 24)] = sW2[i];
    }
    for (int v = tid; v < ASR * 6; v += 256) {
        int t = v / 6, q = (v % 6) * 4;
        int r = m0 + t; if (r > 16383) r = 16383;
        *reinterpret_cast<float4*>(&As[t * 28 + q]) =
            *reinterpret_cast<const float4*>(Ab + (long long)r * 24 + q);
    }
    __syncthreads();

    // ---- stage 1: gated conv of layer 1 over R8 rows ----
    const int w1 = wid * RW;
    float acc1[MI][6][4];
#pragma unroll
    for (int mi = 0; mi < MI; mi++)
#pragma unroll
        for (int ni = 0; ni < 6; ni++)
#pragma unroll
            for (int j = 0; j < 4; j++) acc1[mi][ni][j] = 0.f;

#pragma unroll
    for (int ks = 0; ks < 6; ks++) {
        const int kb   = ks * 8;
        const int roff = (ks < 3) ? 0 : D1;
        const int col  = (ks < 3) ? kb : kb - 24;
        uint32_t a[MI][4];
#pragma unroll
        for (int mi = 0; mi < MI; mi++) {
            const int r = w1 + mi * 16 + lr + roff;
            a[mi][0] = __float_as_uint(As[r * 28 + col + lc]);
            a[mi][1] = __float_as_uint(As[(r + 8) * 28 + col + lc]);
            a[mi][2] = __float_as_uint(As[r * 28 + col + lc + 4]);
            a[mi][3] = __float_as_uint(As[(r + 8) * 28 + col + lc + 4]);
        }
#pragma unroll
        for (int ni = 0; ni < 6; ni++) {
            uint32_t bf[2];
            bf[0] = __float_as_uint(Wc1[(kb + lc) * 56 + ni * 8 + lr]);
            bf[1] = __float_as_uint(Wc1[(kb + lc + 4) * 56 + ni * 8 + lr]);
#pragma unroll
            for (int mi = 0; mi < MI; mi++) mma_tf32_16x8x8(acc1[mi][ni], a[mi], bf);
        }
    }

    // ---- act1 -> P (warp-private rows; As untouched) ----
#pragma unroll
    for (int mi = 0; mi < MI; mi++)
#pragma unroll
        for (int ni = 0; ni < 3; ni++)
#pragma unroll
            for (int j = 0; j < 4; j++) {
                const int c = ni * 8 + 2 * lc + (j & 1);
                const int m = w1 + mi * 16 + lr + ((j >> 1) << 3);
                float g = acc1[mi][ni][j]     + gb1[c];
                float f = acc1[mi][ni + 3][j] + fb1[c];
                P[m * 28 + c] = tanhf(f) * (1.f / (1.f + __expf(-g)));
            }
    __syncwarp();

    // ---- scale1 (row-local) -> mid in place in P ----
    float accs[MI][3][4];
#pragma unroll
    for (int mi = 0; mi < MI; mi++)
#pragma unroll
        for (int ni = 0; ni < 3; ni++)
#pragma unroll
            for (int j = 0; j < 4; j++) accs[mi][ni][j] = 0.f;
#pragma unroll
    for (int ks = 0; ks < 3; ks++) {
        const int kb = ks * 8;
        uint32_t a[MI][4];
#pragma unroll
        for (int mi = 0; mi < MI; mi++) {
            const int r = w1 + mi * 16 + lr;
            a[mi][0] = __float_as_uint(P[r * 28 + kb + lc]);
            a[mi][1] = __float_as_uint(P[(r + 8) * 28 + kb + lc]);
            a[mi][2] = __float_as_uint(P[r * 28 + kb + lc + 4]);
            a[mi][3] = __float_as_uint(P[(r + 8) * 28 + kb + lc + 4]);
        }
#pragma unroll
        for (int ni = 0; ni < 3; ni++) {
            uint32_t bf[2];
            bf[0] = __float_as_uint(W21[(kb + lc) * 40 + ni * 8 + lr]);
            bf[1] = __float_as_uint(W21[(kb + lc + 4) * 40 + ni * 8 + lr]);
#pragma unroll
            for (int mi = 0; mi < MI; mi++) mma_tf32_16x8x8(accs[mi][ni], a[mi], bf);
        }
    }
    __syncwarp();
#pragma unroll
    for (int mi = 0; mi < MI; mi++)
#pragma unroll
        for (int ni = 0; ni < 3; ni++)
#pragma unroll
            for (int j = 0; j < 4; j++) {
                const int c = ni * 8 + 2 * lc + (j & 1);
                const int m = w1 + mi * 16 + lr + ((j >> 1) << 3);
                P[m * 28 + c] = accs[mi][ni][j] + sb1[c];
            }
    __syncthreads();

    // ---- stage 2: gated conv of layer 2 over 256 rows (32/warp) ----
    const int w2 = wid * 32;
    float acc2[2][6][4];
#pragma unroll
    for (int mi = 0; mi < 2; mi++)
#pragma unroll
        for (int ni = 0; ni < 6; ni++)
#pragma unroll
            for (int j = 0; j < 4; j++) acc2[mi][ni][j] = 0.f;

#pragma unroll
    for (int ks = 0; ks < 6; ks++) {
        const int kb   = ks * 8;
        const int roff = (ks < 3) ? 0 : D2;
        const int col  = (ks < 3) ? kb : kb - 24;
        uint32_t a[2][4];
#pragma unroll
        for (int mi = 0; mi < 2; mi++) {
            const int r = w2 + mi * 16 + lr + roff;
            a[mi][0] = __float_as_uint(P[r * 28 + col + lc]);
            a[mi][1] = __float_as_uint(P[(r + 8) * 28 + col + lc]);
            a[mi][2] = __float_as_uint(P[r * 28 + col + lc + 4]);
            a[mi][3] = __float_as_uint(P[(r + 8) * 28 + col + lc + 4]);
        }
#pragma unroll
        for (int ni = 0; ni < 6; ni++) {
            uint32_t bf[2];
            bf[0] = __float_as_uint(Wc2[(kb + lc) * 56 + ni * 8 + lr]);
            bf[1] = __float_as_uint(Wc2[(kb + lc + 4) * 56 + ni * 8 + lr]);
            mma_tf32_16x8x8(acc2[0][ni], a[0], bf);
            mma_tf32_16x8x8(acc2[1][ni], a[1], bf);
        }
    }

    // ---- act2 -> As rows (dead region; fill->stage1 reads were fenced
    //      by the mid->stage2 __syncthreads) ----
#pragma unroll
    for (int mi = 0; mi < 2; mi++)
#pragma unroll
        for (int ni = 0; ni < 3; ni++)
#pragma unroll
            for (int j = 0; j < 4; j++) {
                const int c = ni * 8 + 2 * lc + (j & 1);
                const int m = w2 + mi * 16 + lr + ((j >> 1) << 3);
                float g = acc2[mi][ni][j]     + gb2[c];
                float f = acc2[mi][ni + 3][j] + fb2[c];
                As[m * 28 + c] = tanhf(f) * (1.f / (1.f + __expf(-g)));
            }
    __syncwarp();

    // ---- scale2 (row-local) -> write out ----
    float acc3[2][3][4];
#pragma unroll
    for (int mi = 0; mi < 2; mi++)
#pragma unroll
        for (int ni = 0; ni < 3; ni++)
#pragma unroll
            for (int j = 0; j < 4; j++) acc3[mi][ni][j] = 0.f;
#pragma unroll
    for (int ks = 0; ks < 3; ks++) {
        const int kb = ks * 8;
        uint32_t a[2][4];
#pragma unroll
        for (int mi = 0; mi < 2; mi++) {
            const int r = w2 + mi * 16 + lr;
            a[mi][0] = __float_as_uint(As[r * 28 + kb + lc]);
            a[mi][1] = __float_as_uint(As[(r + 8) * 28 + kb + lc]);
            a[mi][2] = __float_as_uint(As[r * 28 + kb + lc + 4]);
            a[mi][3] = __float_as_uint(As[(r + 8) * 28 + kb + lc + 4]);
        }
#pragma unroll
        for (int ni = 0; ni < 3; ni++) {
            uint32_t bf[2];
            bf[0] = __float_as_uint(W22[(kb + lc) * 40 + ni * 8 + lr]);
            bf[1] = __float_as_uint(W22[(kb + lc + 4) * 40 + ni * 8 + lr]);
            mma_tf32_16x8x8(acc3[0][ni], a[0], bf);
            mma_tf32_16x8x8(acc3[1][ni], a[1], bf);
        }
    }
    float* O = out + (long long)b * 16384 * 24;
#pragma unroll
    for (int mi = 0; mi < 2; mi++) {
        const int r0 = m0 + w2 + mi * 16 + lr;
        const int r1 = r0 + 8;
#pragma unroll
        for (int ni = 0; ni < 3; ni++) {
            const int col = ni * 8 + 2 * lc;
            if (r0 < Lout) {
                float2 o = { acc3[mi][ni][0] + sb2[col], acc3[mi][ni][1] + sb2[col + 1] };
                *reinterpret_cast<float2*>(O + (long long)r0 * 24 + col) = o;
            }
            if (r1 < Lout) {
                float2 o = { acc3[mi][ni][2] + sb2[col], acc3[mi][ni][3] + sb2[col + 1] };
                *reinterpret_cast<float2*>(O + (long long)r1 * 24 + col) = o;
            }
        }
    }
}

// =====================================================================
// LAST dilated layer (d=512) fused with residual + res conv + relu.
// (unchanged from round 9)
// =====================================================================
template<int LAST>
__global__ void __launch_bounds__(256)
gated24b_k(const float* __restrict__ in, float* __restrict__ out,
           int Lout, int d,
           const float* __restrict__ gW, const float* __restrict__ gb,
           const float* __restrict__ fW, const float* __restrict__ fb,
           const float* __restrict__ sW, const float* __restrict__ sb,
           const float* __restrict__ Rg, const float* __restrict__ rb,
           float* __restrict__ outa)
{
    extern __shared__ float smf[];
    float* As = smf;                     // [256][52]
    float* Wc = As + 256 * 52;           // [48][56]
    float* W2 = Wc + 48 * 56;            // [24][40]
    float* T  = W2 + 24 * 40;            // [256][28]
    float* Rw = T + 256 * 28;            // [24][136]
    float* P  = As;                      // alias

    const int b  = blockIdx.y;
    const int m0 = blockIdx.x * 256;
    const float* Ab = in + (long long)b * 16384 * 24;

    const int tid = threadIdx.x;
    const int wid = tid >> 5;
    const int lane = tid & 31;
    const int lr = lane >> 2;
    const int lc = lane & 3;
    const int mrow = wid * 32;

    for (int i = tid; i < 2304; i += 256) {
        int k = i / 48, n = i % 48;
        Wc[k * 56 + n] = (n < 24) ? gW[k * 24 + n] : fW[k * 24 + (n - 24)];
    }
    for (int i = tid; i < 576; i += 256) W2[(i / 24) * 40 + (i % 24)] = sW[i];
    if (LAST) {
        for (int i = tid; i < 768; i += 256) {
            int k = i >> 5, c = (i & 31) * 4;
            *reinterpret_cast<float4*>(&Rw[k * 136 + c]) =
                *reinterpret_cast<const float4*>(Rg + i * 4);
        }
    }

    for (int v = tid; v < 1536; v += 256) {
        int t = v / 6, q = (v % 6) * 4;
        int r0 = m0 + t;
        *reinterpret_cast<float4*>(&As[t * 52 + q]) =
            *reinterpret_cast<const float4*>(Ab + (long long)r0 * 24 + q);
        int r1 = m0 + t + d; if (r1 > 16383) r1 = 16383;
        *reinterpret_cast<float4*>(&As[t * 52 + 24 + q]) =
            *reinterpret_cast<const float4*>(Ab + (long long)r1 * 24 + q);
        if (LAST) {
            *reinterpret_cast<float4*>(&T[t * 28 + q]) =
                *reinterpret_cast<const float4*>(Ab + (long long)(m0 + t + 256) * 24 + q);
        }
    }
    __syncthreads();

    float acc[2][6][4];
#pragma unroll
    for (int mi = 0; mi < 2; mi++)
#pragma unroll
        for (int ni = 0; ni < 6; ni++)
#pragma unroll
            for (int j = 0; j < 4; j++) acc[mi][ni][j] = 0.f;

#pragma unroll
    for (int ks = 0; ks < 6; ks++) {
        const int kb = ks * 8;
        uint32_t a[2][4];
#pragma unroll
        for (int mi = 0; mi < 2; mi++) {
            const int r = mrow + mi * 16 + lr;
            a[mi][0] = __float_as_uint(As[r * 52 + kb + lc]);
            a[mi][1] = __float_as_uint(As[(r + 8) * 52 + kb + lc]);
            a[mi][2] = __float_as_uint(As[r * 52 + kb + lc + 4]);
            a[mi][3] = __float_as_uint(As[(r + 8) * 52 + kb + lc + 4]);
        }
#pragma unroll
        for (int ni = 0; ni < 6; ni++) {
            uint32_t bf[2];
            bf[0] = __float_as_uint(Wc[(kb + lc) * 56 + ni * 8 + lr]);
            bf[1] = __float_as_uint(Wc[(kb + lc + 4) * 56 + ni * 8 + lr]);
            mma_tf32_16x8x8(acc[0][ni], a[0], bf);
            mma_tf32_16x8x8(acc[1][ni], a[1], bf);
        }
    }
    __syncthreads();

#pragma unroll
    for (int mi = 0; mi < 2; mi++)
#pragma unroll
        for (int ni = 0; ni < 3; ni++)
#pragma unroll
            for (int j = 0; j < 4; j++) {
                const int c = ni * 8 + 2 * lc + (j & 1);
                const int m = mrow + mi * 16 + lr + ((j >> 1) << 3);
                float g = acc[mi][ni][j]     + gb[c];
                float f = acc[mi][ni + 3][j] + fb[c];
                P[m * 28 + c] = tanhf(f) * (1.f / (1.f + __expf(-g)));
            }
    __syncwarp();

    float acc2[2][3][4];
#pragma unroll
    for (int mi = 0; mi < 2; mi++)
#pragma unroll
        for (int ni = 0; ni < 3; ni++)
#pragma unroll
            for (int j = 0; j < 4; j++) acc2[mi][ni][j] = 0.f;

#pragma unroll
    for (int ks = 0; ks < 3; ks++) {
        const int kb = ks * 8;
        uint32_t a[2][4];
#pragma unroll
        for (int mi = 0; mi < 2; mi++) {
            const int r = mrow + mi * 16 + lr;
            a[mi][0] = __float_as_uint(P[r * 28 + kb + lc]);
            a[mi][1] = __float_as_uint(P[(r + 8) * 28 + kb + lc]);
            a[mi][2] = __float_as_uint(P[r * 28 + kb + lc + 4]);
            a[mi][3] = __float_as_uint(P[(r + 8) * 28 + kb + lc + 4]);
        }
#pragma unroll
        for (int ni = 0; ni < 3; ni++) {
            uint32_t bf[2];
            bf[0] = __float_as_uint(W2[(kb + lc) * 40 + ni * 8 + lr]);
            bf[1] = __float_as_uint(W2[(kb + lc + 4) * 40 + ni * 8 + lr]);
            mma_tf32_16x8x8(acc2[0][ni], a[0], bf);
            mma_tf32_16x8x8(acc2[1][ni], a[1], bf);
        }
    }

    {
#pragma unroll
        for (int mi = 0; mi < 2; mi++)
#pragma unroll
            for (int ni = 0; ni < 3; ni++)
#pragma unroll
                for (int j = 0; j < 4; j++) {
                    const int c = ni * 8 + 2 * lc + (j & 1);
                    const int m = mrow + mi * 16 + lr + ((j >> 1) << 3);
                    P[m * 28 + c] = acc2[mi][ni][j] + sb[c] + T[m * 28 + c];
                }
        __syncwarp();

        float* O = outa + (long long)b * 15360 * 128 + (long long)m0 * 128;
#pragma unroll
        for (int h = 0; h < 2; h++) {
            float acc3[2][8][4];
#pragma unroll
            for (int mi = 0; mi < 2; mi++)
#pragma unroll
                for (int ni = 0; ni < 8; ni++)
#pragma unroll
                    for (int j = 0; j < 4; j++) acc3[mi][ni][j] = 0.f;

#pragma unroll
            for (int ks = 0; ks < 3; ks++) {
                const int kb = ks * 8;
                uint32_t a[2][4];
#pragma unroll
                for (int mi = 0; mi < 2; mi++) {
                    const int r = mrow + mi * 16 + lr;
                    a[mi][0] = __float_as_uint(P[r * 28 + kb + lc]);
                    a[mi][1] = __float_as_uint(P[(r + 8) * 28 + kb + lc]);
                    a[mi][2] = __float_as_uint(P[r * 28 + kb + lc + 4]);
                    a[mi][3] = __float_as_uint(P[(r + 8) * 28 + kb + lc + 4]);
                }
#pragma unroll
                for (int ni = 0; ni < 8; ni++) {
                    uint32_t bf[2];
                    bf[0] = __float_as_uint(Rw[(kb + lc) * 136 + h * 64 + ni * 8 + lr]);
                    bf[1] = __float_as_uint(Rw[(kb + lc + 4) * 136 + h * 64 + ni * 8 + lr]);
                    mma_tf32_16x8x8(acc3[0][ni], a[0], bf);
                    mma_tf32_16x8x8(acc3[1][ni], a[1], bf);
                }
            }
#pragma unroll
            for (int mi = 0; mi < 2; mi++) {
                const int r0 = mrow + mi * 16 + lr;
                const int r1 = r0 + 8;
#pragma unroll
                for (int ni = 0; ni < 8; ni++) {
                    const int col = h * 64 + ni * 8 + 2 * lc;
                    float2 o0 = { fmaxf(acc3[mi][ni][0] + rb[col], 0.f),
                                  fmaxf(acc3[mi][ni][1] + rb[col + 1], 0.f) };
                    *reinterpret_cast<float2*>(O + (long long)r0 * 128 + col) = o0;
                    float2 o1 = { fmaxf(acc3[mi][ni][2] + rb[col], 0.f),
                                  fmaxf(acc3[mi][ni][3] + rb[col + 1], 0.f) };
                    *reinterpret_cast<float2*>(O + (long long)r1 * 128 + col) = o1;
                }
            }
        }
    }
}

// =====================================================================
// First gated layer, tensorized + cp.async pipelined (A AND B) over K=512.
// =====================================================================
__global__ void __launch_bounds__(256)
first_gated_mma_k(const float* __restrict__ h0,
                  const float* __restrict__ gW, const float* __restrict__ gb,
                  const float* __restrict__ fW, const float* __restrict__ fb,
                  const float* __restrict__ sW, const float* __restrict__ sb,
                  float* __restrict__ out)
{
    __shared__ __align__(16) float As[2][128][20];
    __shared__ __align__(16) float Bs[2][16][56];
    __shared__ float W2[24][56];
    float* P = &As[0][0][0];

    const int M  = 16382;
    const int b  = blockIdx.y;
    const int m0 = blockIdx.x * 128;
    const float* A = h0 + (long long)b * 16384 * 256;

    const int tid = threadIdx.x;
    const int wid = tid >> 5;
    const int lane = tid & 31;
    const int lr = lane >> 2;
    const int lc = lane & 3;
    const int mrow = wid * 16;

    const int arow_ld = tid >> 1;
    const int akq     = (tid & 1) * 8;
    int mg = m0 + arow_ld; if (mg > M - 1) mg = M - 1;
    const float* Ap = A + (long long)mg * 256;

    // B cp.async mapping: 192 threads, 1 x 16B each
    const int bh = tid / 96;                 // 0: gW, 1: fW (valid for tid<192)
    const int bu = tid - bh * 96;
    const int brr = bu / 6, bq = (bu % 6) * 4;

    for (int i = tid; i < 576; i += 256) W2[i / 24][i % 24] = sW[i];

    if (tid < 192) {
        const float* src = (bh ? fW : gW) + (long long)brr * 24 + bq;
        cpa16(&Bs[0][brr][bh * 24 + bq], src);
    }
    cpa16(&As[0][arow_ld][akq],     Ap + akq);
    cpa16(&As[0][arow_ld][akq + 4], Ap + akq + 4);
    CP_COMMIT();

    float acc[6][4];
#pragma unroll
    for (int ni = 0; ni < 6; ni++)
#pragma unroll
        for (int j = 0; j < 4; j++) acc[ni][j] = 0.f;

#pragma unroll 1
    for (int ic = 0; ic < 32; ic++) {
        const int s = ic & 1;
        if (ic < 31) {
            const int k1 = (ic + 1) * 16;
            if (tid < 192) {
                const float* src = (bh ? fW : gW) + (long long)(k1 + brr) * 24 + bq;
                cpa16(&Bs[s ^ 1][brr][bh * 24 + bq], src);
            }
            cpa16(&As[s ^ 1][arow_ld][akq],     Ap + k1 + akq);
            cpa16(&As[s ^ 1][arow_ld][akq + 4], Ap + k1 + akq + 4);
            CP_COMMIT();
            CP_WAIT1();
        } else {
            CP_WAIT0();
        }
        __syncthreads();

#pragma unroll
        for (int ks = 0; ks < 2; ks++) {
            const int kb = ks * 8;
            uint32_t a[4];
            a[0] = __float_as_uint(As[s][mrow + lr][kb + lc]);
            a[1] = __float_as_uint(As[s][mrow + lr + 8][kb + lc]);
            a[2] = __float_as_uint(As[s][mrow + lr][kb + lc + 4]);
            a[3] = __float_as_uint(As[s][mrow + lr + 8][kb + lc + 4]);
#pragma unroll
            for (int ni = 0; ni < 6; ni++) {
                uint32_t bf[2];
                bf[0] = __float_as_uint(Bs[s][kb + lc][ni * 8 + lr]);
                bf[1] = __float_as_uint(Bs[s][kb + lc + 4][ni * 8 + lr]);
                mma_tf32_16x8x8(acc[ni], a, bf);
            }
        }
        __syncthreads();
    }

#pragma unroll
    for (int ni = 0; ni < 3; ni++) {
        const int col = ni * 8 + 2 * lc;
#pragma unroll
        for (int j = 0; j < 4; j++) {
            const int c = col + (j & 1);
            float g = acc[ni][j]     + gb[c];
            float f = acc[ni + 3][j] + fb[c];
            float p = tanhf(f) * (1.f / (1.f + __expf(-g)));
            const int m = mrow + lr + ((j >> 1) << 3);
            P[m * 28 + c] = p;
        }
    }
    __syncthreads();

    float acc2[3][4];
#pragma unroll
    for (int ni = 0; ni < 3; ni++)
#pragma unroll
        for (int j = 0; j < 4; j++) acc2[ni][j] = 0.f;

#pragma unroll
    for (int ks = 0; ks < 3; ks++) {
        const int kb = ks * 8;
        uint32_t a[4];
        a[0] = __float_as_uint(P[(mrow + lr) * 28 + kb + lc]);
        a[1] = __float_as_uint(P[(mrow + lr + 8) * 28 + kb + lc]);
        a[2] = __float_as_uint(P[(mrow + lr) * 28 + kb + lc + 4]);
        a[3] = __float_as_uint(P[(mrow + lr + 8) * 28 + kb + lc + 4]);
#pragma unroll
        for (int ni = 0; ni < 3; ni++) {
            uint32_t bf[2];
            bf[0] = __float_as_uint(W2[kb + lc][ni * 8 + lr]);
            bf[1] = __float_as_uint(W2[kb + lc + 4][ni * 8 + lr]);
            mma_tf32_16x8x8(acc2[ni], a, bf);
        }
    }

    float* O = out + (long long)b * 16384 * 24;
    const int r0 = m0 + mrow + lr;
    const int r1 = r0 + 8;
#pragma unroll
    for (int ni = 0; ni < 3; ni++) {
        const int col = ni * 8 + 2 * lc;
        if (r0 < M) {
            float2 o = { acc2[ni][0] + sb[col], acc2[ni][1] + sb[col + 1] };
            *reinterpret_cast<float2*>(O + (long long)r0 * 24 + col) = o;
        }
        if (r1 < M) {
            float2 o = { acc2[ni][2] + sb[col], acc2[ni][3] + sb[col + 1] };
            *reinterpret_cast<float2*>(O + (long long)r1 * 24 + col) = o;
        }
    }
}

// =====================================================================
template<int D1, int D2>
static inline int pair_smem_bytes() {
    constexpr int MM  = 256 + D2;
    constexpr int RW  = ((MM + 127) / 128) * 16;
    constexpr int R8  = RW * 8;
    constexpr int ASR = R8 + D1;
    return (ASR * 28 + R8 * 28 + 2 * (48 * 56 + 24 * 40)) * 4;
}

extern "C" void kernel_launch(void* const* d_in, const int* in_sizes, int n_in,
                              void* d_out, int out_size)
{
    const float* x        = (const float*)d_in[0];
    const float* causal_W = (const float*)d_in[1];
    const float* causal_b = (const float*)d_in[2];
    const float* gW0      = (const float*)d_in[3];
    const float* gb0      = (const float*)d_in[4];
    const float* fW0      = (const float*)d_in[5];
    const float* fb0      = (const float*)d_in[6];
    const float* sW0      = (const float*)d_in[7];
    const float* sb0      = (const float*)d_in[8];
    const float* gate_W   = (const float*)d_in[9];
    const float* gate_b   = (const float*)d_in[10];
    const float* filter_W = (const float*)d_in[11];
    const float* filter_b = (const float*)d_in[12];
    const float* scale_W  = (const float*)d_in[13];
    const float* scale_b  = (const float*)d_in[14];
    const float* res_W    = (const float*)d_in[15];
    const float* res_b    = (const float*)d_in[16];
    const float* f1_W     = (const float*)d_in[17];
    const float* f1_b     = (const float*)d_in[18];
    const float* f2_W     = (const float*)d_in[19];
    const float* f2_b     = (const float*)d_in[20];
    float* out = (float*)d_out;

    float *h0, *p0, *p1, *accb, *a2b;
    cudaGetSymbolAddress((void**)&h0,   g_h0);
    cudaGetSymbolAddress((void**)&p0,   g_p0);
    cudaGetSymbolAddress((void**)&p1,   g_p1);
    cudaGetSymbolAddress((void**)&accb, g_accb);
    cudaGetSymbolAddress((void**)&a2b,  g_a2);

    const int GEMM_SMEM  = (2 * 128 * 20 + 2 * 16 * 264) * 4;
    const int G24L_SMEM  = (256 * 52 + 48 * 56 + 24 * 40 + 256 * 28 + 24 * 136) * 4;
    const int SMP1 = pair_smem_bytes<2, 4>();
    const int SMP2 = pair_smem_bytes<8, 16>();
    const int SMP3 = pair_smem_bytes<32, 64>();
    const int SMP4 = pair_smem_bytes<128, 256>();

    cudaFuncSetAttribute(mma_gemm_k<0>, cudaFuncAttributeMaxDynamicSharedMemorySize, GEMM_SMEM);
    cudaFuncSetAttribute(mma_gemm_k<1>, cudaFuncAttributeMaxDynamicSharedMemorySize, GEMM_SMEM);
    cudaFuncSetAttribute(mma_gemm_k<2>, cudaFuncAttributeMaxDynamicSharedMemorySize, GEMM_SMEM);
    cudaFuncSetAttribute(gated24b_k<1>, cudaFuncAttributeMaxDynamicSharedMemorySize, G24L_SMEM);
    cudaFuncSetAttribute(gated24_pair_k<2, 4>,     cudaFuncAttributeMaxDynamicSharedMemorySize, SMP1);
    cudaFuncSetAttribute(gated24_pair_k<8, 16>,    cudaFuncAttributeMaxDynamicSharedMemorySize, SMP2);
    cudaFuncSetAttribute(gated24_pair_k<32, 64>,   cudaFuncAttributeMaxDynamicSharedMemorySize, SMP3);
    cudaFuncSetAttribute(gated24_pair_k<128, 256>, cudaFuncAttributeMaxDynamicSharedMemorySize, SMP4);

    // 1) causal conv as pipelined tf32 mma GEMM: per-batch M=16383, K=512
    mma_gemm_k<0><<<dim3(1, 128, 8), 256, GEMM_SMEM>>>(
        x, 16384LL * 256, 16383, 512, 256, causal_W, causal_b, h0, 16384LL * 256, 256);

    // 2) first gated layer -> p0 (16382 rows/batch)
    first_gated_mma_k<<<dim3(128, 8), 256>>>(h0, gW0, gb0, fW0, fb0, sW0, sb0, p0);

    // 3) dilated layers 0..7 as 4 pair-fused kernels
    //    Lin=16382; Louts: 16376, 16352, 16256, 15872
    gated24_pair_k<2, 4><<<dim3(64, 8), 256, SMP1>>>(
        p0, p1, 16376,
        gate_W + 0 * 1152, gate_b + 0 * 24, filter_W + 0 * 1152, filter_b + 0 * 24,
        scale_W + 0 * 576, scale_b + 0 * 24,
        gate_W + 1 * 1152, gate_b + 1 * 24, filter_W + 1 * 1152, filter_b + 1 * 24,
        scale_W + 1 * 576, scale_b + 1 * 24);
    gated24_pair_k<8, 16><<<dim3(64, 8), 256, SMP2>>>(
        p1, p0, 16352,
        gate_W + 2 * 1152, gate_b + 2 * 24, filter_W + 2 * 1152, filter_b + 2 * 24,
        scale_W + 2 * 576, scale_b + 2 * 24,
        gate_W + 3 * 1152, gate_b + 3 * 24, filter_W + 3 * 1152, filter_b + 3 * 24,
        scale_W + 3 * 576, scale_b + 3 * 24);
    gated24_pair_k<32, 64><<<dim3(64, 8), 256, SMP3>>>(
        p0, p1, 16256,
        gate_W + 4 * 1152, gate_b + 4 * 24, filter_W + 4 * 1152, filter_b + 4 * 24,
        scale_W + 4 * 576, scale_b + 4 * 24,
        gate_W + 5 * 1152, gate_b + 5 * 24, filter_W + 5 * 1152, filter_b + 5 * 24,
        scale_W + 5 * 576, scale_b + 5 * 24);
    gated24_pair_k<128, 256><<<dim3(62, 8), 256, SMP4>>>(
        p1, p0, 15872,
        gate_W + 6 * 1152, gate_b + 6 * 24, filter_W + 6 * 1152, filter_b + 6 * 24,
        scale_W + 6 * 576, scale_b + 6 * 24,
        gate_W + 7 * 1152, gate_b + 7 * 24, filter_W + 7 * 1152, filter_b + 7 * 24,
        scale_W + 7 * 576, scale_b + 7 * 24);

    // layer 8 (d=512): fused gated + residual + res conv + relu -> accb
    gated24b_k<1><<<dim3(60, 8), 256, G24L_SMEM>>>(
        p0, nullptr, 15360, 512,
        gate_W + 8 * 1152, gate_b + 8 * 24,
        filter_W + 8 * 1152, filter_b + 8 * 24,
        scale_W + 8 * 576, scale_b + 8 * 24,
        res_W + 8 * 3072, res_b + 8 * 128, accb);

    // 4) f1: pipelined tf32 GEMM K=128 + ReLU -> a2b (122880 x 256)
    mma_gemm_k<1><<<dim3(1, 960, 1), 256, GEMM_SMEM>>>(
        accb, 0, 122880, 128, 128, f1_W, f1_b, a2b, 0, 256);

    // 5) f2: pipelined tf32 GEMM K=256 + fused softmax -> d_out
    mma_gemm_k<2><<<dim3(1, 960, 1), 256, GEMM_SMEM>>>(
        a2b, 0, 122880, 256, 256, f2_W, f2_b, out, 0, 256);
}